// round 1
// baseline (speedup 1.0000x reference)
#include <cuda_runtime.h>
#include <cuda_bf16.h>
#include <cstddef>

// Problem constants
#define BB 4
#define LL 2048
#define DD 1024
#define HH 16
#define HD 64
#define MM (BB * LL)          // 8192 rows
#define D3 (3 * DD)           // 3072

// Scratch (device globals -- no allocation allowed in kernel_launch)
__device__ float g_qkv[(size_t)MM * D3];   // [B*L, 3*D]
__device__ float g_att[(size_t)MM * DD];   // [B*L, D]  (attention out, b l (h d))

// ============================================================================
// SGEMM NT:  C[M,N] = A[M,K] @ B[N,K]^T      (both A and B are K-contiguous)
// BM=BN=128, BK=16, 256 threads, 8x8 microtile per thread.
// ============================================================================
__global__ __launch_bounds__(256) void sgemm_nt_kernel(
    const float* __restrict__ A, const float* __restrict__ B,
    float* __restrict__ C, int Mn, int Nn, int Kn)
{
    __shared__ __align__(16) float As[16][132];
    __shared__ __align__(16) float Bs[16][132];

    const int tid = threadIdx.x;
    const int tx = tid & 15;          // 16 col-groups of 8
    const int ty = tid >> 4;          // 16 row-groups of 8
    const int bm = blockIdx.y * 128;
    const int bn = blockIdx.x * 128;

    float acc[8][8];
#pragma unroll
    for (int i = 0; i < 8; i++)
#pragma unroll
        for (int j = 0; j < 8; j++) acc[i][j] = 0.f;

    for (int kt = 0; kt < Kn; kt += 16) {
        // Fill As/Bs (transposed to [k][m]/[k][n]): 512 float4 each, 2 per thread
#pragma unroll
        for (int it = 0; it < 2; it++) {
            const int f   = tid + it * 256;     // float4 index 0..511
            const int row = f >> 2;             // 0..127
            const int k4  = (f & 3) * 4;        // 0,4,8,12
            float4 va = *(const float4*)&A[(size_t)(bm + row) * Kn + kt + k4];
            As[k4 + 0][row] = va.x; As[k4 + 1][row] = va.y;
            As[k4 + 2][row] = va.z; As[k4 + 3][row] = va.w;
            float4 vb = *(const float4*)&B[(size_t)(bn + row) * Kn + kt + k4];
            Bs[k4 + 0][row] = vb.x; Bs[k4 + 1][row] = vb.y;
            Bs[k4 + 2][row] = vb.z; Bs[k4 + 3][row] = vb.w;
        }
        __syncthreads();

#pragma unroll
        for (int k = 0; k < 16; k++) {
            float4 a0 = *(const float4*)&As[k][ty * 8];
            float4 a1 = *(const float4*)&As[k][ty * 8 + 4];
            float4 b0 = *(const float4*)&Bs[k][tx * 8];
            float4 b1 = *(const float4*)&Bs[k][tx * 8 + 4];
            float a[8] = {a0.x, a0.y, a0.z, a0.w, a1.x, a1.y, a1.z, a1.w};
            float b[8] = {b0.x, b0.y, b0.z, b0.w, b1.x, b1.y, b1.z, b1.w};
#pragma unroll
            for (int i = 0; i < 8; i++)
#pragma unroll
                for (int j = 0; j < 8; j++)
                    acc[i][j] += a[i] * b[j];
        }
        __syncthreads();
    }

#pragma unroll
    for (int i = 0; i < 8; i++) {
        const size_t row = (size_t)(bm + ty * 8 + i);
#pragma unroll
        for (int j = 0; j < 8; j += 4) {
            float4 v = make_float4(acc[i][j], acc[i][j + 1], acc[i][j + 2], acc[i][j + 3]);
            *(float4*)&C[row * Nn + bn + tx * 8 + j] = v;
        }
    }
}

// ============================================================================
// Flash attention (fp32, causal, online softmax).
// Grid: (L/64 q-tiles, B*H). Block: 256 threads.
// Q tile: 64 rows. KV tile: 32 rows. O accumulators in registers (4x4/thread).
// K-tile smem (transposed) is reused as the P (=softmax(S)) tile.
// ============================================================================
#define SCALE 0.125f   // 64^-0.5

__global__ __launch_bounds__(256) void flash_kernel(
    const float* __restrict__ qkv, float* __restrict__ out)
{
    const int bh = blockIdx.y;
    const int b  = bh >> 4;
    const int h  = bh & 15;
    const int qbase = blockIdx.x * 64;

    const float* baseq = qkv + (size_t)b * LL * D3 + h * HD;
    const float* basek = baseq + DD;
    const float* basev = baseq + 2 * DD;

    __shared__ __align__(16) float Qt[64 * 64];     // Qt[d*64 + r]      (transposed Q)
    __shared__ __align__(16) float KtPs[64 * 34];   // Kt[d*34 + c]  OR  Ps[r*34 + c]
    __shared__ __align__(16) float Vs[32 * 68];     // Vs[c*68 + d]
    __shared__ float m_s[64], l_s[64], al_s[64];

    const int tid = threadIdx.x;
    const int tx  = tid & 15;     // S cols: tx*2 .. +1 ; O cols: tx*4 .. +3
    const int ty  = tid >> 4;     // rows:   ty*4 .. +3

    // ---- Load Q tile transposed (coalesced gmem, scatter smem) ----
#pragma unroll
    for (int it = 0; it < 4; it++) {
        const int f  = tid + it * 256;     // float4 index, 1024 total
        const int r  = f >> 4;             // q row 0..63
        const int d4 = (f & 15) * 4;
        float4 v = *(const float4*)&baseq[(size_t)(qbase + r) * D3 + d4];
        Qt[(d4 + 0) * 64 + r] = v.x;
        Qt[(d4 + 1) * 64 + r] = v.y;
        Qt[(d4 + 2) * 64 + r] = v.z;
        Qt[(d4 + 3) * 64 + r] = v.w;
    }
    if (tid < 64) { m_s[tid] = -1e30f; l_s[tid] = 0.f; }

    float o[4][4];
#pragma unroll
    for (int i = 0; i < 4; i++)
#pragma unroll
        for (int j = 0; j < 4; j++) o[i][j] = 0.f;

    const int ntiles = (qbase >> 5) + 2;   // kv tiles of 32 covering [0, qbase+64)

    for (int t = 0; t < ntiles; t++) {
        const int kvbase = t * 32;
        __syncthreads();   // protects KtPs/Vs reuse + init visibility

        // ---- Load K (transposed) and V tiles: 32 x 64 each ----
#pragma unroll
        for (int it = 0; it < 2; it++) {
            const int f  = tid + it * 256;
            const int r  = f >> 4;           // kv row 0..31
            const int d4 = (f & 15) * 4;
            float4 kv4 = *(const float4*)&basek[(size_t)(kvbase + r) * D3 + d4];
            KtPs[(d4 + 0) * 34 + r] = kv4.x;
            KtPs[(d4 + 1) * 34 + r] = kv4.y;
            KtPs[(d4 + 2) * 34 + r] = kv4.z;
            KtPs[(d4 + 3) * 34 + r] = kv4.w;
            float4 vv = *(const float4*)&basev[(size_t)(kvbase + r) * D3 + d4];
            *(float4*)&Vs[r * 68 + d4] = vv;
        }
        __syncthreads();

        // ---- S = Q K^T  (4 rows x 2 cols per thread) ----
        float s00 = 0.f, s01 = 0.f, s10 = 0.f, s11 = 0.f;
        float s20 = 0.f, s21 = 0.f, s30 = 0.f, s31 = 0.f;
#pragma unroll
        for (int d = 0; d < 64; d++) {
            float4 a = *(const float4*)&Qt[d * 64 + ty * 4];
            float b0 = KtPs[d * 34 + tx * 2];
            float b1 = KtPs[d * 34 + tx * 2 + 1];
            s00 += a.x * b0; s01 += a.x * b1;
            s10 += a.y * b0; s11 += a.y * b1;
            s20 += a.z * b0; s21 += a.z * b1;
            s30 += a.w * b0; s31 += a.w * b1;
        }

        // scale + causal mask
        const int rg = qbase + ty * 4;
        const int cg = kvbase + tx * 2;
        float sv[4][2] = {{s00, s01}, {s10, s11}, {s20, s21}, {s30, s31}};
#pragma unroll
        for (int i = 0; i < 4; i++)
#pragma unroll
            for (int j = 0; j < 2; j++) {
                float v = sv[i][j] * SCALE;
                if (cg + j > rg + i) v = -1e30f;
                sv[i][j] = v;
            }

        __syncthreads();   // all Kt reads done -> safe to overwrite as Ps
#pragma unroll
        for (int i = 0; i < 4; i++) {
            KtPs[(ty * 4 + i) * 34 + tx * 2]     = sv[i][0];
            KtPs[(ty * 4 + i) * 34 + tx * 2 + 1] = sv[i][1];
        }
        __syncthreads();

        // ---- Online softmax: one thread per row ----
        if (tid < 64) {
            float* pr = &KtPs[tid * 34];
            float mo = m_s[tid];
            float tm = -1e30f;
#pragma unroll
            for (int c = 0; c < 32; c++) tm = fmaxf(tm, pr[c]);
            const float mn = fmaxf(mo, tm);
            const float al = __expf(mo - mn);
            float ls = 0.f;
#pragma unroll
            for (int c = 0; c < 32; c++) {
                float p = __expf(pr[c] - mn);
                pr[c] = p;
                ls += p;
            }
            m_s[tid]  = mn;
            l_s[tid]  = l_s[tid] * al + ls;
            al_s[tid] = al;
        }
        __syncthreads();

        // ---- O = O*alpha + P @ V  (4 rows x 4 d-cols per thread) ----
        float alr[4];
#pragma unroll
        for (int i = 0; i < 4; i++) alr[i] = al_s[ty * 4 + i];
#pragma unroll
        for (int i = 0; i < 4; i++)
#pragma unroll
            for (int j = 0; j < 4; j++) o[i][j] *= alr[i];

#pragma unroll
        for (int c = 0; c < 32; c++) {
            float p0 = KtPs[(ty * 4 + 0) * 34 + c];
            float p1 = KtPs[(ty * 4 + 1) * 34 + c];
            float p2 = KtPs[(ty * 4 + 2) * 34 + c];
            float p3 = KtPs[(ty * 4 + 3) * 34 + c];
            float4 v = *(const float4*)&Vs[c * 68 + tx * 4];
            o[0][0] += p0 * v.x; o[0][1] += p0 * v.y; o[0][2] += p0 * v.z; o[0][3] += p0 * v.w;
            o[1][0] += p1 * v.x; o[1][1] += p1 * v.y; o[1][2] += p1 * v.z; o[1][3] += p1 * v.w;
            o[2][0] += p2 * v.x; o[2][1] += p2 * v.y; o[2][2] += p2 * v.z; o[2][3] += p2 * v.w;
            o[3][0] += p3 * v.x; o[3][1] += p3 * v.y; o[3][2] += p3 * v.z; o[3][3] += p3 * v.w;
        }
    }

    // ---- Write O / l  to g_att in 'b l (h d)' layout ----
#pragma unroll
    for (int i = 0; i < 4; i++) {
        const int r = ty * 4 + i;
        const float invl = 1.0f / l_s[r];
        float4 v = make_float4(o[i][0] * invl, o[i][1] * invl,
                               o[i][2] * invl, o[i][3] * invl);
        *(float4*)&out[((size_t)b * LL + qbase + r) * DD + h * HD + tx * 4] = v;
    }
}

// ============================================================================
// Launch
// ============================================================================
extern "C" void kernel_launch(void* const* d_in, const int* in_sizes, int n_in,
                              void* d_out, int out_size)
{
    const float* x    = (const float*)d_in[0];
    const float* Wqkv = (const float*)d_in[1];
    const float* Wout = (const float*)d_in[2];
    // safety: identify weights by element count if order differs
    if (n_in >= 3 && in_sizes[1] == DD * DD && in_sizes[2] == 3 * DD * DD) {
        const float* t = Wqkv; Wqkv = Wout; Wout = t;
    }
    float* out = (float*)d_out;

    float* qkv = nullptr;
    float* att = nullptr;
    cudaGetSymbolAddress((void**)&qkv, g_qkv);
    cudaGetSymbolAddress((void**)&att, g_att);

    // 1) QKV projection: [8192,1024] @ [3072,1024]^T -> [8192,3072]
    sgemm_nt_kernel<<<dim3(D3 / 128, MM / 128), 256>>>(x, Wqkv, qkv, MM, D3, DD);

    // 2) Causal flash attention -> [8192,1024] in (b l (h d)) layout
    flash_kernel<<<dim3(LL / 64, BB * HH), 256>>>(qkv, att);

    // 3) Output projection: [8192,1024] @ [1024,1024]^T -> d_out
    sgemm_nt_kernel<<<dim3(DD / 128, MM / 128), 256>>>(att, Wout, out, MM, DD, DD);
}

// round 5
// speedup vs baseline: 1.2458x; 1.2458x over previous
#include <cuda_runtime.h>
#include <cuda_bf16.h>
#include <cstdint>
#include <cstddef>

// Problem constants
#define BB 4
#define LL 2048
#define DD 1024
#define HH 16
#define HD 64
#define MM (BB * LL)          // 8192
#define D3 (3 * DD)           // 3072

// ---------------------------------------------------------------------------
// Scratch (device globals)
// ---------------------------------------------------------------------------
__device__ float g_qkv[(size_t)MM * D3];   // [B*L, 3D] fp32 (flash input)
__device__ float g_att[(size_t)MM * DD];   // [B*L, D]  fp32 (attention out)

__device__ __nv_bfloat16 g_xh[(size_t)MM * DD],  g_xl[(size_t)MM * DD];
__device__ __nv_bfloat16 g_wqh[(size_t)D3 * DD], g_wql[(size_t)D3 * DD];
__device__ __nv_bfloat16 g_woh[(size_t)DD * DD], g_wol[(size_t)DD * DD];
__device__ __nv_bfloat16 g_ah[(size_t)MM * DD],  g_al[(size_t)MM * DD];

// ---------------------------------------------------------------------------
// fp32 -> (bf16 hi, bf16 lo) split
// ---------------------------------------------------------------------------
__global__ __launch_bounds__(256) void split_kernel(
    const float* __restrict__ src, __nv_bfloat16* __restrict__ hi,
    __nv_bfloat16* __restrict__ lo, int n4)
{
    const int i = blockIdx.x * blockDim.x + threadIdx.x;
    if (i >= n4) return;
    float4 v = *(const float4*)(src + (size_t)i * 4);
    __nv_bfloat16 h0 = __float2bfloat16(v.x);
    __nv_bfloat16 h1 = __float2bfloat16(v.y);
    __nv_bfloat16 h2 = __float2bfloat16(v.z);
    __nv_bfloat16 h3 = __float2bfloat16(v.w);
    __nv_bfloat16 l0 = __float2bfloat16(v.x - __bfloat162float(h0));
    __nv_bfloat16 l1 = __float2bfloat16(v.y - __bfloat162float(h1));
    __nv_bfloat16 l2 = __float2bfloat16(v.z - __bfloat162float(h2));
    __nv_bfloat16 l3 = __float2bfloat16(v.w - __bfloat162float(h3));
    __nv_bfloat162* hp = (__nv_bfloat162*)(hi + (size_t)i * 4);
    __nv_bfloat162* lp = (__nv_bfloat162*)(lo + (size_t)i * 4);
    hp[0] = __halves2bfloat162(h0, h1);
    hp[1] = __halves2bfloat162(h2, h3);
    lp[0] = __halves2bfloat162(l0, l1);
    lp[1] = __halves2bfloat162(l2, l3);
}

// ---------------------------------------------------------------------------
// mma.sync bf16x3 GEMM:  C[M,N] = Ahi@Bhi^T + Ahi@Blo^T + Alo@Bhi^T  (fp32)
// Tile: BM=128, BN=128, BK=32. 256 threads = 8 warps (2m x 4n), warp 64x32.
// Effective K = 3 * 1024 (hi/lo segment concatenation).
// cp.async.cg double-buffered; smem row stride 80B (conflict-free ldmatrix).
// ---------------------------------------------------------------------------
#define ROWB 80                      // smem bytes per tile row (64 data + 16 pad)
#define TILEB (128 * ROWB)           // 10240 bytes per tile
#define KT_TOT 96                    // 3 * 1024 / 32

__device__ __forceinline__ void cp16(uint32_t saddr, const void* gaddr) {
    asm volatile("cp.async.cg.shared.global [%0], [%1], 16;"
                 :: "r"(saddr), "l"(gaddr));
}
__device__ __forceinline__ void cp_commit() {
    asm volatile("cp.async.commit_group;" ::: "memory");
}
__device__ __forceinline__ void cp_wait1() {
    asm volatile("cp.async.wait_group 1;" ::: "memory");
}
__device__ __forceinline__ void ldsm4(uint32_t& r0, uint32_t& r1, uint32_t& r2,
                                      uint32_t& r3, uint32_t addr) {
    asm volatile("ldmatrix.sync.aligned.m8n8.x4.shared.b16 {%0,%1,%2,%3}, [%4];"
                 : "=r"(r0), "=r"(r1), "=r"(r2), "=r"(r3) : "r"(addr));
}
__device__ __forceinline__ void mma16816(float* d, uint32_t a0, uint32_t a1,
                                         uint32_t a2, uint32_t a3,
                                         uint32_t b0, uint32_t b1) {
    asm volatile(
        "mma.sync.aligned.m16n8k16.row.col.f32.bf16.bf16.f32 "
        "{%0,%1,%2,%3}, {%4,%5,%6,%7}, {%8,%9}, {%0,%1,%2,%3};"
        : "+f"(d[0]), "+f"(d[1]), "+f"(d[2]), "+f"(d[3])
        : "r"(a0), "r"(a1), "r"(a2), "r"(a3), "r"(b0), "r"(b1));
}

__global__ __launch_bounds__(256) void gemm_bf16x3_kernel(
    const __nv_bfloat16* __restrict__ Ahi, const __nv_bfloat16* __restrict__ Alo,
    const __nv_bfloat16* __restrict__ Bhi, const __nv_bfloat16* __restrict__ Blo,
    float* __restrict__ C, int Nn)
{
    __shared__ __align__(16) char smem[4 * TILEB];   // Abuf0 Bbuf0 Abuf1 Bbuf1

    const int tid  = threadIdx.x;
    const int lane = tid & 31;
    const int wid  = tid >> 5;
    const int wm   = wid & 1;       // 0,1   -> m offset 0/64
    const int wn   = wid >> 1;      // 0..3  -> n offset 0/32/64/96
    const int bm   = blockIdx.y * 128;
    const int bn   = blockIdx.x * 128;

    uint32_t sb;
    asm("{ .reg .u64 t; cvta.to.shared.u64 t, %1; cvt.u32.u64 %0, t; }"
        : "=r"(sb) : "l"((const void*)smem));
    const uint32_t sA[2] = {sb, sb + 2 * TILEB};
    const uint32_t sB[2] = {sb + TILEB, sb + 3 * TILEB};

    // per-thread load mapping: 2 chunks of 16B for A and B each
    const int f0 = tid * 2;
    const int r0_ = f0 >> 2, c0_ = f0 & 3;
    const int r1_ = (f0 + 1) >> 2, c1_ = (f0 + 1) & 3;

    // ldmatrix lane offsets
    const uint32_t lm_row = (lane & 15);
    const uint32_t lm_hi  = (lane >> 4) * 16;
    const uint32_t a_base = (wm * 64 + lm_row) * ROWB + lm_hi;
    const uint32_t b_base = (wn * 32 + lm_row) * ROWB + lm_hi;

    float acc[4][4][4];
#pragma unroll
    for (int i = 0; i < 4; i++)
#pragma unroll
        for (int j = 0; j < 4; j++)
#pragma unroll
            for (int k = 0; k < 4; k++) acc[i][j][k] = 0.f;

    auto issue_loads = [&](int kt, int buf) {
        const __nv_bfloat16* Ap = (kt < 64) ? Ahi : Alo;
        const __nv_bfloat16* Bp = (kt < 32) ? Bhi : ((kt < 64) ? Blo : Bhi);
        const int k0 = (kt & 31) * 32;
        cp16(sA[buf] + r0_ * ROWB + c0_ * 16, Ap + (size_t)(bm + r0_) * DD + k0 + c0_ * 8);
        cp16(sA[buf] + r1_ * ROWB + c1_ * 16, Ap + (size_t)(bm + r1_) * DD + k0 + c1_ * 8);
        cp16(sB[buf] + r0_ * ROWB + c0_ * 16, Bp + (size_t)(bn + r0_) * DD + k0 + c0_ * 8);
        cp16(sB[buf] + r1_ * ROWB + c1_ * 16, Bp + (size_t)(bn + r1_) * DD + k0 + c1_ * 8);
    };

    issue_loads(0, 0); cp_commit();
    issue_loads(1, 1); cp_commit();

    for (int kt = 0; kt < KT_TOT; kt++) {
        const int buf = kt & 1;
        cp_wait1();
        __syncthreads();

#pragma unroll
        for (int s = 0; s < 2; s++) {           // two k16 steps in BK=32
            uint32_t a[4][4];
#pragma unroll
            for (int mf = 0; mf < 4; mf++)
                ldsm4(a[mf][0], a[mf][1], a[mf][2], a[mf][3],
                      sA[buf] + a_base + mf * 16 * ROWB + s * 32);
            uint32_t b[2][4];
#pragma unroll
            for (int bh = 0; bh < 2; bh++)
                ldsm4(b[bh][0], b[bh][1], b[bh][2], b[bh][3],
                      sB[buf] + b_base + bh * 16 * ROWB + s * 32);
#pragma unroll
            for (int mf = 0; mf < 4; mf++) {
#pragma unroll
                for (int nf = 0; nf < 4; nf++) {
                    const int bh = nf >> 1, sub = nf & 1;
                    mma16816(acc[mf][nf], a[mf][0], a[mf][1], a[mf][2], a[mf][3],
                             sub ? b[bh][1] : b[bh][0],
                             sub ? b[bh][3] : b[bh][2]);
                }
            }
        }
        __syncthreads();
        if (kt + 2 < KT_TOT) issue_loads(kt + 2, buf);
        cp_commit();                   // empty group when nothing issued (keeps count)
    }

    // Epilogue: fp32 store. c0/c1: row=lane>>2, col=(lane&3)*2; c2/c3: row+8
    const int er = lane >> 2;
    const int ec = (lane & 3) * 2;
#pragma unroll
    for (int mf = 0; mf < 4; mf++) {
        const size_t row0 = (size_t)(bm + wm * 64 + mf * 16 + er) * Nn + bn + wn * 32;
        const size_t row8 = row0 + (size_t)8 * Nn;
#pragma unroll
        for (int nf = 0; nf < 4; nf++) {
            *(float2*)(C + row0 + nf * 8 + ec) = make_float2(acc[mf][nf][0], acc[mf][nf][1]);
            *(float2*)(C + row8 + nf * 8 + ec) = make_float2(acc[mf][nf][2], acc[mf][nf][3]);
        }
    }
}

// ---------------------------------------------------------------------------
// Flash attention (fp32, causal, online softmax) -- unchanged
// ---------------------------------------------------------------------------
#define SCALE 0.125f

__global__ __launch_bounds__(256) void flash_kernel(
    const float* __restrict__ qkv, float* __restrict__ out)
{
    const int bh = blockIdx.y;
    const int b  = bh >> 4;
    const int h  = bh & 15;
    const int qbase = blockIdx.x * 64;

    const float* baseq = qkv + (size_t)b * LL * D3 + h * HD;
    const float* basek = baseq + DD;
    const float* basev = baseq + 2 * DD;

    __shared__ __align__(16) float Qt[64 * 64];
    __shared__ __align__(16) float KtPs[64 * 34];
    __shared__ __align__(16) float Vs[32 * 68];
    __shared__ float m_s[64], l_s[64], al_s[64];

    const int tid = threadIdx.x;
    const int tx  = tid & 15;
    const int ty  = tid >> 4;

#pragma unroll
    for (int it = 0; it < 4; it++) {
        const int f  = tid + it * 256;
        const int r  = f >> 4;
        const int d4 = (f & 15) * 4;
        float4 v = *(const float4*)&baseq[(size_t)(qbase + r) * D3 + d4];
        Qt[(d4 + 0) * 64 + r] = v.x;
        Qt[(d4 + 1) * 64 + r] = v.y;
        Qt[(d4 + 2) * 64 + r] = v.z;
        Qt[(d4 + 3) * 64 + r] = v.w;
    }
    if (tid < 64) { m_s[tid] = -1e30f; l_s[tid] = 0.f; }

    float o[4][4];
#pragma unroll
    for (int i = 0; i < 4; i++)
#pragma unroll
        for (int j = 0; j < 4; j++) o[i][j] = 0.f;

    const int ntiles = (qbase >> 5) + 2;

    for (int t = 0; t < ntiles; t++) {
        const int kvbase = t * 32;
        __syncthreads();

#pragma unroll
        for (int it = 0; it < 2; it++) {
            const int f  = tid + it * 256;
            const int r  = f >> 4;
            const int d4 = (f & 15) * 4;
            float4 kv4 = *(const float4*)&basek[(size_t)(kvbase + r) * D3 + d4];
            KtPs[(d4 + 0) * 34 + r] = kv4.x;
            KtPs[(d4 + 1) * 34 + r] = kv4.y;
            KtPs[(d4 + 2) * 34 + r] = kv4.z;
            KtPs[(d4 + 3) * 34 + r] = kv4.w;
            float4 vv = *(const float4*)&basev[(size_t)(kvbase + r) * D3 + d4];
            *(float4*)&Vs[r * 68 + d4] = vv;
        }
        __syncthreads();

        float s00 = 0.f, s01 = 0.f, s10 = 0.f, s11 = 0.f;
        float s20 = 0.f, s21 = 0.f, s30 = 0.f, s31 = 0.f;
#pragma unroll
        for (int d = 0; d < 64; d++) {
            float4 a = *(const float4*)&Qt[d * 64 + ty * 4];
            float b0 = KtPs[d * 34 + tx * 2];
            float b1 = KtPs[d * 34 + tx * 2 + 1];
            s00 += a.x * b0; s01 += a.x * b1;
            s10 += a.y * b0; s11 += a.y * b1;
            s20 += a.z * b0; s21 += a.z * b1;
            s30 += a.w * b0; s31 += a.w * b1;
        }

        const int rg = qbase + ty * 4;
        const int cg = kvbase + tx * 2;
        float sv[4][2] = {{s00, s01}, {s10, s11}, {s20, s21}, {s30, s31}};
#pragma unroll
        for (int i = 0; i < 4; i++)
#pragma unroll
            for (int j = 0; j < 2; j++) {
                float v = sv[i][j] * SCALE;
                if (cg + j > rg + i) v = -1e30f;
                sv[i][j] = v;
            }

        __syncthreads();
#pragma unroll
        for (int i = 0; i < 4; i++) {
            KtPs[(ty * 4 + i) * 34 + tx * 2]     = sv[i][0];
            KtPs[(ty * 4 + i) * 34 + tx * 2 + 1] = sv[i][1];
        }
        __syncthreads();

        if (tid < 64) {
            float* pr = &KtPs[tid * 34];
            float mo = m_s[tid];
            float tm = -1e30f;
#pragma unroll
            for (int c = 0; c < 32; c++) tm = fmaxf(tm, pr[c]);
            const float mn = fmaxf(mo, tm);
            const float al = __expf(mo - mn);
            float ls = 0.f;
#pragma unroll
            for (int c = 0; c < 32; c++) {
                float p = __expf(pr[c] - mn);
                pr[c] = p;
                ls += p;
            }
            m_s[tid]  = mn;
            l_s[tid]  = l_s[tid] * al + ls;
            al_s[tid] = al;
        }
        __syncthreads();

        float alr[4];
#pragma unroll
        for (int i = 0; i < 4; i++) alr[i] = al_s[ty * 4 + i];
#pragma unroll
        for (int i = 0; i < 4; i++)
#pragma unroll
            for (int j = 0; j < 4; j++) o[i][j] *= alr[i];

#pragma unroll
        for (int c = 0; c < 32; c++) {
            float p0 = KtPs[(ty * 4 + 0) * 34 + c];
            float p1 = KtPs[(ty * 4 + 1) * 34 + c];
            float p2 = KtPs[(ty * 4 + 2) * 34 + c];
            float p3 = KtPs[(ty * 4 + 3) * 34 + c];
            float4 v = *(const float4*)&Vs[c * 68 + tx * 4];
            o[0][0] += p0 * v.x; o[0][1] += p0 * v.y; o[0][2] += p0 * v.z; o[0][3] += p0 * v.w;
            o[1][0] += p1 * v.x; o[1][1] += p1 * v.y; o[1][2] += p1 * v.z; o[1][3] += p1 * v.w;
            o[2][0] += p2 * v.x; o[2][1] += p2 * v.y; o[2][2] += p2 * v.z; o[2][3] += p2 * v.w;
            o[3][0] += p3 * v.x; o[3][1] += p3 * v.y; o[3][2] += p3 * v.z; o[3][3] += p3 * v.w;
        }
    }

#pragma unroll
    for (int i = 0; i < 4; i++) {
        const int r = ty * 4 + i;
        const float invl = 1.0f / l_s[r];
        float4 v = make_float4(o[i][0] * invl, o[i][1] * invl,
                               o[i][2] * invl, o[i][3] * invl);
        *(float4*)&out[((size_t)b * LL + qbase + r) * DD + h * HD + tx * 4] = v;
    }
}

// ---------------------------------------------------------------------------
// Launch
// ---------------------------------------------------------------------------
extern "C" void kernel_launch(void* const* d_in, const int* in_sizes, int n_in,
                              void* d_out, int out_size)
{
    const float* x    = (const float*)d_in[0];
    const float* Wqkv = (const float*)d_in[1];
    const float* Wout = (const float*)d_in[2];
    if (n_in >= 3 && in_sizes[1] == DD * DD && in_sizes[2] == 3 * DD * DD) {
        const float* t = Wqkv; Wqkv = Wout; Wout = t;
    }
    float* out = (float*)d_out;

    float *qkv, *att;
    __nv_bfloat16 *xh, *xl, *wqh, *wql, *woh, *wol, *ah, *al;
    cudaGetSymbolAddress((void**)&qkv, g_qkv);
    cudaGetSymbolAddress((void**)&att, g_att);
    cudaGetSymbolAddress((void**)&xh, g_xh);   cudaGetSymbolAddress((void**)&xl, g_xl);
    cudaGetSymbolAddress((void**)&wqh, g_wqh); cudaGetSymbolAddress((void**)&wql, g_wql);
    cudaGetSymbolAddress((void**)&woh, g_woh); cudaGetSymbolAddress((void**)&wol, g_wol);
    cudaGetSymbolAddress((void**)&ah, g_ah);   cudaGetSymbolAddress((void**)&al, g_al);

    // Split inputs to (hi, lo) bf16
    split_kernel<<<(MM * DD / 4 + 255) / 256, 256>>>(x, xh, xl, MM * DD / 4);
    split_kernel<<<(D3 * DD / 4 + 255) / 256, 256>>>(Wqkv, wqh, wql, D3 * DD / 4);
    split_kernel<<<(DD * DD / 4 + 255) / 256, 256>>>(Wout, woh, wol, DD * DD / 4);

    // 1) QKV projection: [8192,1024] @ [3072,1024]^T  (bf16x3 on HMMA)
    gemm_bf16x3_kernel<<<dim3(D3 / 128, MM / 128), 256>>>(xh, xl, wqh, wql, qkv, D3);

    // 2) Causal flash attention (fp32)
    flash_kernel<<<dim3(LL / 64, BB * HH), 256>>>(qkv, att);

    // 3) Split attention output, then output projection
    split_kernel<<<(MM * DD / 4 + 255) / 256, 256>>>(att, ah, al, MM * DD / 4);
    gemm_bf16x3_kernel<<<dim3(DD / 128, MM / 128), 256>>>(ah, al, woh, wol, out, DD);
}

// round 6
// speedup vs baseline: 2.0613x; 1.6546x over previous
#include <cuda_runtime.h>
#include <cuda_bf16.h>
#include <cstdint>
#include <cstddef>

// Problem constants
#define BB 4
#define LL 2048
#define DD 1024
#define HH 16
#define HD 64
#define MM (BB * LL)          // 8192
#define D3 (3 * DD)           // 3072

// ---------------------------------------------------------------------------
// Scratch (device globals)
// ---------------------------------------------------------------------------
__device__ __nv_bfloat16 g_qkvh[(size_t)MM * D3], g_qkvl[(size_t)MM * D3];
__device__ __nv_bfloat16 g_xh[(size_t)MM * DD],  g_xl[(size_t)MM * DD];
__device__ __nv_bfloat16 g_wqh[(size_t)D3 * DD], g_wql[(size_t)D3 * DD];
__device__ __nv_bfloat16 g_woh[(size_t)DD * DD], g_wol[(size_t)DD * DD];
__device__ __nv_bfloat16 g_ah[(size_t)MM * DD],  g_al[(size_t)MM * DD];

// ---------------------------------------------------------------------------
// Common helpers
// ---------------------------------------------------------------------------
__device__ __forceinline__ uint32_t smem_u32(const void* p) {
    uint32_t a;
    asm("{ .reg .u64 t; cvta.to.shared.u64 t, %1; cvt.u32.u64 %0, t; }"
        : "=r"(a) : "l"(p));
    return a;
}
__device__ __forceinline__ void cp16(uint32_t saddr, const void* gaddr) {
    asm volatile("cp.async.cg.shared.global [%0], [%1], 16;"
                 :: "r"(saddr), "l"(gaddr));
}
__device__ __forceinline__ void cp_commit() {
    asm volatile("cp.async.commit_group;" ::: "memory");
}
template<int N> __device__ __forceinline__ void cp_wait() {
    asm volatile("cp.async.wait_group %0;" :: "n"(N) : "memory");
}
__device__ __forceinline__ void ldsm4(uint32_t& r0, uint32_t& r1, uint32_t& r2,
                                      uint32_t& r3, uint32_t addr) {
    asm volatile("ldmatrix.sync.aligned.m8n8.x4.shared.b16 {%0,%1,%2,%3}, [%4];"
                 : "=r"(r0), "=r"(r1), "=r"(r2), "=r"(r3) : "r"(addr));
}
__device__ __forceinline__ void ldsm4t(uint32_t& r0, uint32_t& r1, uint32_t& r2,
                                       uint32_t& r3, uint32_t addr) {
    asm volatile("ldmatrix.sync.aligned.m8n8.x4.trans.shared.b16 {%0,%1,%2,%3}, [%4];"
                 : "=r"(r0), "=r"(r1), "=r"(r2), "=r"(r3) : "r"(addr));
}
__device__ __forceinline__ void mma16816(float* d, const uint32_t* a,
                                         uint32_t b0, uint32_t b1) {
    asm volatile(
        "mma.sync.aligned.m16n8k16.row.col.f32.bf16.bf16.f32 "
        "{%0,%1,%2,%3}, {%4,%5,%6,%7}, {%8,%9}, {%0,%1,%2,%3};"
        : "+f"(d[0]), "+f"(d[1]), "+f"(d[2]), "+f"(d[3])
        : "r"(a[0]), "r"(a[1]), "r"(a[2]), "r"(a[3]), "r"(b0), "r"(b1));
}
// pack (x,y) to bf16x2 hi, produce bf16x2 lo residual
__device__ __forceinline__ uint32_t packhl(float x, float y, uint32_t& lo) {
    __nv_bfloat162 hv = __floats2bfloat162_rn(x, y);
    float hx = __bfloat162float(__low2bfloat16(hv));
    float hy = __bfloat162float(__high2bfloat16(hv));
    __nv_bfloat162 lv = __floats2bfloat162_rn(x - hx, y - hy);
    lo = *(uint32_t*)&lv;
    return *(uint32_t*)&hv;
}

// ---------------------------------------------------------------------------
// fp32 -> (bf16 hi, bf16 lo) split (for x and weights)
// ---------------------------------------------------------------------------
__global__ __launch_bounds__(256) void split_kernel(
    const float* __restrict__ src, __nv_bfloat16* __restrict__ hi,
    __nv_bfloat16* __restrict__ lo, int n4)
{
    const int i = blockIdx.x * blockDim.x + threadIdx.x;
    if (i >= n4) return;
    float4 v = *(const float4*)(src + (size_t)i * 4);
    uint32_t l0, l1;
    uint32_t h0 = packhl(v.x, v.y, l0);
    uint32_t h1 = packhl(v.z, v.w, l1);
    *(uint2*)(hi + (size_t)i * 4) = make_uint2(h0, h1);
    *(uint2*)(lo + (size_t)i * 4) = make_uint2(l0, l1);
}

// ---------------------------------------------------------------------------
// mma.sync bf16x3 GEMM, 4-stage cp.async pipeline.
// C = Ahi@Bhi^T + Ahi@Blo^T + Alo@Bhi^T. BM=BN=128, BK=32, 8 warps (2m x 4n).
// MODE 0: fp32 C out. MODE 1: bf16 hi/lo out, cols < 1024 scaled by 0.125.
// ---------------------------------------------------------------------------
#define ROWB 80
#define TILEB (128 * ROWB)            // 10240
#define STAGEB (2 * TILEB)            // 20480 (A + B)
#define GSMEM (4 * STAGEB)            // 81920
#define KT_TOT 96

template<int MODE>
__global__ __launch_bounds__(256) void gemm_bf16x3_kernel(
    const __nv_bfloat16* __restrict__ Ahi, const __nv_bfloat16* __restrict__ Alo,
    const __nv_bfloat16* __restrict__ Bhi, const __nv_bfloat16* __restrict__ Blo,
    float* __restrict__ C, __nv_bfloat16* __restrict__ Ch,
    __nv_bfloat16* __restrict__ Cl, int Nn)
{
    extern __shared__ char smem[];
    const int tid  = threadIdx.x;
    const int lane = tid & 31;
    const int wid  = tid >> 5;
    const int wm   = wid & 1;
    const int wn   = wid >> 1;
    const int bm   = blockIdx.y * 128;
    const int bn   = blockIdx.x * 128;

    const uint32_t sb = smem_u32(smem);

    const int f0 = tid * 2;
    const int r0_ = f0 >> 2, c0_ = f0 & 3;
    const int r1_ = (f0 + 1) >> 2, c1_ = (f0 + 1) & 3;

    const uint32_t lm_row = (lane & 15);
    const uint32_t lm_hi  = (lane >> 4) * 16;
    const uint32_t a_base = (wm * 64 + lm_row) * ROWB + lm_hi;
    const uint32_t b_base = (wn * 32 + lm_row) * ROWB + lm_hi;

    float acc[4][4][4];
#pragma unroll
    for (int i = 0; i < 4; i++)
#pragma unroll
        for (int j = 0; j < 4; j++)
#pragma unroll
            for (int k = 0; k < 4; k++) acc[i][j][k] = 0.f;

    auto issue_loads = [&](int kt) {
        const int buf = kt & 3;
        const uint32_t sa = sb + buf * STAGEB;
        const uint32_t sbm = sa + TILEB;
        const __nv_bfloat16* Ap = (kt < 64) ? Ahi : Alo;
        const __nv_bfloat16* Bp = (kt < 32) ? Bhi : ((kt < 64) ? Blo : Bhi);
        const int k0 = (kt & 31) * 32;
        cp16(sa + r0_ * ROWB + c0_ * 16, Ap + (size_t)(bm + r0_) * DD + k0 + c0_ * 8);
        cp16(sa + r1_ * ROWB + c1_ * 16, Ap + (size_t)(bm + r1_) * DD + k0 + c1_ * 8);
        cp16(sbm + r0_ * ROWB + c0_ * 16, Bp + (size_t)(bn + r0_) * DD + k0 + c0_ * 8);
        cp16(sbm + r1_ * ROWB + c1_ * 16, Bp + (size_t)(bn + r1_) * DD + k0 + c1_ * 8);
    };

    issue_loads(0); cp_commit();
    issue_loads(1); cp_commit();
    issue_loads(2); cp_commit();

    for (int kt = 0; kt < KT_TOT; kt++) {
        cp_wait<2>();
        __syncthreads();
        if (kt + 3 < KT_TOT) issue_loads(kt + 3);
        cp_commit();

        const uint32_t sa = sb + (kt & 3) * STAGEB;
        const uint32_t sbm = sa + TILEB;
#pragma unroll
        for (int s = 0; s < 2; s++) {
            uint32_t a[4][4];
#pragma unroll
            for (int mf = 0; mf < 4; mf++)
                ldsm4(a[mf][0], a[mf][1], a[mf][2], a[mf][3],
                      sa + a_base + mf * 16 * ROWB + s * 32);
            uint32_t b[2][4];
#pragma unroll
            for (int bh2 = 0; bh2 < 2; bh2++)
                ldsm4(b[bh2][0], b[bh2][1], b[bh2][2], b[bh2][3],
                      sbm + b_base + bh2 * 16 * ROWB + s * 32);
#pragma unroll
            for (int mf = 0; mf < 4; mf++) {
#pragma unroll
                for (int nf = 0; nf < 4; nf++) {
                    const int bh2 = nf >> 1, sub = nf & 1;
                    uint32_t bb0 = sub ? b[bh2][1] : b[bh2][0];
                    uint32_t bb1 = sub ? b[bh2][3] : b[bh2][2];
                    mma16816(acc[mf][nf], a[mf], bb0, bb1);
                }
            }
        }
    }

    // Epilogue
    const int er = lane >> 2;
    const int ec = (lane & 3) * 2;
    const float qs = (MODE == 1 && bn < DD) ? 0.125f : 1.0f;
#pragma unroll
    for (int mf = 0; mf < 4; mf++) {
        const size_t row0 = (size_t)(bm + wm * 64 + mf * 16 + er) * Nn + bn + wn * 32;
        const size_t row8 = row0 + (size_t)8 * Nn;
#pragma unroll
        for (int nf = 0; nf < 4; nf++) {
            if (MODE == 0) {
                *(float2*)(C + row0 + nf * 8 + ec) = make_float2(acc[mf][nf][0], acc[mf][nf][1]);
                *(float2*)(C + row8 + nf * 8 + ec) = make_float2(acc[mf][nf][2], acc[mf][nf][3]);
            } else {
                uint32_t lo;
                uint32_t hi = packhl(acc[mf][nf][0] * qs, acc[mf][nf][1] * qs, lo);
                *(uint32_t*)(Ch + row0 + nf * 8 + ec) = hi;
                *(uint32_t*)(Cl + row0 + nf * 8 + ec) = lo;
                hi = packhl(acc[mf][nf][2] * qs, acc[mf][nf][3] * qs, lo);
                *(uint32_t*)(Ch + row8 + nf * 8 + ec) = hi;
                *(uint32_t*)(Cl + row8 + nf * 8 + ec) = lo;
            }
        }
    }
}

// ---------------------------------------------------------------------------
// Flash attention on HMMA, split bf16 precision everywhere, fp32 softmax.
// CTA: 128 q-rows, 8 warps x 16 rows. KV tile 64. Q pre-scaled by 0.125.
// Writes O as bf16 hi/lo directly (input for the out-projection GEMM).
// ---------------------------------------------------------------------------
#define FROWB 144

__global__ __launch_bounds__(256) void flash_hmma_kernel(
    const __nv_bfloat16* __restrict__ qh_, const __nv_bfloat16* __restrict__ ql_,
    __nv_bfloat16* __restrict__ oh_, __nv_bfloat16* __restrict__ ol_)
{
    __shared__ __align__(16) char fs[4 * 64 * FROWB];   // 36864
    const int bh = blockIdx.y;
    const int b  = bh >> 4;
    const int h  = bh & 15;
    const int qbase = blockIdx.x * 128;
    const int tid = threadIdx.x, lane = tid & 31, w = tid >> 5;
    const uint32_t sb = smem_u32(fs);

    // ---- Load Q tile (128 x 64 bf16, hi+lo) into smem ----
    const size_t qrow0 = (size_t)b * LL + qbase;
#pragma unroll
    for (int it = 0; it < 8; it++) {
        const int f = it * 256 + tid;                   // 0..2047
        const __nv_bfloat16* src = (f & 1024) ? ql_ : qh_;
        const int idx = f & 1023, r = idx >> 3, c = idx & 7;
        uint4 v = *(const uint4*)(src + (qrow0 + r) * D3 + h * HD + c * 8);
        *(uint4*)(fs + ((f >> 10) ? 18432 : 0) + r * FROWB + c * 16) = v;
    }
    __syncthreads();

    // ---- Extract Q A-fragments (4 k16 chunks, hi+lo) ----
    uint32_t qfh[4][4], qfl[4][4];
    {
        const uint32_t qa = sb + (uint32_t)((w * 16 + (lane & 15)) * FROWB
                                            + ((lane >> 4) * 16));
#pragma unroll
        for (int kc = 0; kc < 4; kc++) {
            ldsm4(qfh[kc][0], qfh[kc][1], qfh[kc][2], qfh[kc][3], qa + kc * 32);
            ldsm4(qfl[kc][0], qfl[kc][1], qfl[kc][2], qfl[kc][3],
                  qa + 18432 + kc * 32);
        }
    }

    float o[8][4];
#pragma unroll
    for (int i = 0; i < 8; i++)
#pragma unroll
        for (int j = 0; j < 4; j++) o[i][j] = 0.f;
    float m0 = -1e30f, m1 = -1e30f, l0 = 0.f, l1 = 0.f;
    const int row0 = qbase + w * 16 + (lane >> 2);
    const int ntiles = (qbase >> 6) + 2;

    for (int t = 0; t < ntiles; t++) {
        const int kvbase = t * 64;
        __syncthreads();
        // ---- Load K,V hi/lo tiles (64 x 64 bf16 each) ----
#pragma unroll
        for (int it = 0; it < 8; it++) {
            const int f = it * 256 + tid;               // 0..2047
            const int arr = f >> 9, idx = f & 511, r = idx >> 3, c = idx & 7;
            const __nv_bfloat16* src = (arr & 1) ? ql_ : qh_;
            const int colb = (arr < 2) ? (DD + h * HD) : (2 * DD + h * HD);
            uint4 v = *(const uint4*)(src + ((size_t)b * LL + kvbase + r) * D3
                                      + colb + c * 8);
            *(uint4*)(fs + arr * 9216 + r * FROWB + c * 16) = v;
        }
        __syncthreads();

        if (kvbase > qbase + w * 16 + 15) continue;     // fully masked for warp

        // ---- S = Qh Kh^T + Qh Kl^T + Ql Kh^T ----
        float s[8][4];
#pragma unroll
        for (int i = 0; i < 8; i++)
#pragma unroll
            for (int j = 0; j < 4; j++) s[i][j] = 0.f;
#pragma unroll
        for (int nt2 = 0; nt2 < 4; nt2++) {
#pragma unroll
            for (int kc = 0; kc < 4; kc++) {
                uint32_t kh4[4], kl4[4];
                const uint32_t ka = sb + (uint32_t)((nt2 * 16 + (lane & 15)) * FROWB
                                    + ((lane >> 4) * 16) + kc * 32);
                ldsm4(kh4[0], kh4[1], kh4[2], kh4[3], ka);
                ldsm4(kl4[0], kl4[1], kl4[2], kl4[3], ka + 9216);
                mma16816(s[2 * nt2],     qfh[kc], kh4[0], kh4[2]);
                mma16816(s[2 * nt2],     qfh[kc], kl4[0], kl4[2]);
                mma16816(s[2 * nt2],     qfl[kc], kh4[0], kh4[2]);
                mma16816(s[2 * nt2 + 1], qfh[kc], kh4[1], kh4[3]);
                mma16816(s[2 * nt2 + 1], qfh[kc], kl4[1], kl4[3]);
                mma16816(s[2 * nt2 + 1], qfl[kc], kh4[1], kh4[3]);
            }
        }

        // ---- Causal mask ----
        if (kvbase + 63 > qbase + w * 16) {
#pragma unroll
            for (int t8 = 0; t8 < 8; t8++) {
                const int c0 = kvbase + t8 * 8 + (lane & 3) * 2;
                if (c0 > row0)         s[t8][0] = -1e30f;
                if (c0 + 1 > row0)     s[t8][1] = -1e30f;
                if (c0 > row0 + 8)     s[t8][2] = -1e30f;
                if (c0 + 1 > row0 + 8) s[t8][3] = -1e30f;
            }
        }

        // ---- Online softmax (registers + shfl) ----
        float tm0 = -1e30f, tm1 = -1e30f;
#pragma unroll
        for (int t8 = 0; t8 < 8; t8++) {
            tm0 = fmaxf(tm0, fmaxf(s[t8][0], s[t8][1]));
            tm1 = fmaxf(tm1, fmaxf(s[t8][2], s[t8][3]));
        }
        tm0 = fmaxf(tm0, __shfl_xor_sync(0xFFFFFFFFu, tm0, 1));
        tm0 = fmaxf(tm0, __shfl_xor_sync(0xFFFFFFFFu, tm0, 2));
        tm1 = fmaxf(tm1, __shfl_xor_sync(0xFFFFFFFFu, tm1, 1));
        tm1 = fmaxf(tm1, __shfl_xor_sync(0xFFFFFFFFu, tm1, 2));
        const float mn0 = fmaxf(m0, tm0), mn1 = fmaxf(m1, tm1);
        const float a0 = __expf(m0 - mn0), a1 = __expf(m1 - mn1);
        m0 = mn0; m1 = mn1;
        float rs0 = 0.f, rs1 = 0.f;
#pragma unroll
        for (int t8 = 0; t8 < 8; t8++) {
            s[t8][0] = __expf(s[t8][0] - m0);
            s[t8][1] = __expf(s[t8][1] - m0);
            s[t8][2] = __expf(s[t8][2] - m1);
            s[t8][3] = __expf(s[t8][3] - m1);
            rs0 += s[t8][0] + s[t8][1];
            rs1 += s[t8][2] + s[t8][3];
        }
        l0 = l0 * a0 + rs0;
        l1 = l1 * a1 + rs1;
#pragma unroll
        for (int dt = 0; dt < 8; dt++) {
            o[dt][0] *= a0; o[dt][1] *= a0;
            o[dt][2] *= a1; o[dt][3] *= a1;
        }

        // ---- P -> bf16 hi/lo A-fragments ----
        uint32_t ph[4][4], pl[4][4];
#pragma unroll
        for (int kc = 0; kc < 4; kc++) {
            ph[kc][0] = packhl(s[2 * kc][0],     s[2 * kc][1],     pl[kc][0]);
            ph[kc][1] = packhl(s[2 * kc][2],     s[2 * kc][3],     pl[kc][1]);
            ph[kc][2] = packhl(s[2 * kc + 1][0], s[2 * kc + 1][1], pl[kc][2]);
            ph[kc][3] = packhl(s[2 * kc + 1][2], s[2 * kc + 1][3], pl[kc][3]);
        }

        // ---- O += Ph Vh + Ph Vl + Pl Vh (V via ldmatrix.trans) ----
#pragma unroll
        for (int dt2 = 0; dt2 < 4; dt2++) {
#pragma unroll
            for (int kc = 0; kc < 4; kc++) {
                uint32_t vh4[4], vl4[4];
                const uint32_t va = sb + 18432
                    + (uint32_t)((kc * 16 + ((lane >> 3) & 1) * 8 + (lane & 7)) * FROWB
                                 + (dt2 * 16 + (lane >> 4) * 8) * 2);
                ldsm4t(vh4[0], vh4[1], vh4[2], vh4[3], va);
                ldsm4t(vl4[0], vl4[1], vl4[2], vl4[3], va + 9216);
                mma16816(o[2 * dt2],     ph[kc], vh4[0], vh4[1]);
                mma16816(o[2 * dt2 + 1], ph[kc], vh4[2], vh4[3]);
                mma16816(o[2 * dt2],     ph[kc], vl4[0], vl4[1]);
                mma16816(o[2 * dt2 + 1], ph[kc], vl4[2], vl4[3]);
                mma16816(o[2 * dt2],     pl[kc], vh4[0], vh4[1]);
                mma16816(o[2 * dt2 + 1], pl[kc], vh4[2], vh4[3]);
            }
        }
    }

    // ---- Finalize: reduce l across row group, normalize, write hi/lo bf16 ----
    l0 += __shfl_xor_sync(0xFFFFFFFFu, l0, 1);
    l0 += __shfl_xor_sync(0xFFFFFFFFu, l0, 2);
    l1 += __shfl_xor_sync(0xFFFFFFFFu, l1, 1);
    l1 += __shfl_xor_sync(0xFFFFFFFFu, l1, 2);
    const float inv0 = 1.f / l0, inv1 = 1.f / l1;
    const size_t gr0 = (size_t)b * LL + qbase + w * 16 + (lane >> 2);
    const int gc0 = h * HD + (lane & 3) * 2;
#pragma unroll
    for (int t8 = 0; t8 < 8; t8++) {
        uint32_t lo;
        uint32_t hi = packhl(o[t8][0] * inv0, o[t8][1] * inv0, lo);
        *(uint32_t*)(oh_ + gr0 * DD + gc0 + t8 * 8) = hi;
        *(uint32_t*)(ol_ + gr0 * DD + gc0 + t8 * 8) = lo;
        hi = packhl(o[t8][2] * inv1, o[t8][3] * inv1, lo);
        *(uint32_t*)(oh_ + (gr0 + 8) * DD + gc0 + t8 * 8) = hi;
        *(uint32_t*)(ol_ + (gr0 + 8) * DD + gc0 + t8 * 8) = lo;
    }
}

// ---------------------------------------------------------------------------
// Launch
// ---------------------------------------------------------------------------
extern "C" void kernel_launch(void* const* d_in, const int* in_sizes, int n_in,
                              void* d_out, int out_size)
{
    const float* x    = (const float*)d_in[0];
    const float* Wqkv = (const float*)d_in[1];
    const float* Wout = (const float*)d_in[2];
    if (n_in >= 3 && in_sizes[1] == DD * DD && in_sizes[2] == 3 * DD * DD) {
        const float* t = Wqkv; Wqkv = Wout; Wout = t;
    }
    float* out = (float*)d_out;

    __nv_bfloat16 *qkvh, *qkvl, *xh, *xl, *wqh, *wql, *woh, *wol, *ah, *al;
    cudaGetSymbolAddress((void**)&qkvh, g_qkvh); cudaGetSymbolAddress((void**)&qkvl, g_qkvl);
    cudaGetSymbolAddress((void**)&xh, g_xh);     cudaGetSymbolAddress((void**)&xl, g_xl);
    cudaGetSymbolAddress((void**)&wqh, g_wqh);   cudaGetSymbolAddress((void**)&wql, g_wql);
    cudaGetSymbolAddress((void**)&woh, g_woh);   cudaGetSymbolAddress((void**)&wol, g_wol);
    cudaGetSymbolAddress((void**)&ah, g_ah);     cudaGetSymbolAddress((void**)&al, g_al);

    cudaFuncSetAttribute(gemm_bf16x3_kernel<0>,
                         cudaFuncAttributeMaxDynamicSharedMemorySize, GSMEM);
    cudaFuncSetAttribute(gemm_bf16x3_kernel<1>,
                         cudaFuncAttributeMaxDynamicSharedMemorySize, GSMEM);

    // Split inputs to (hi, lo) bf16
    split_kernel<<<(MM * DD / 4 + 255) / 256, 256>>>(x, xh, xl, MM * DD / 4);
    split_kernel<<<(D3 * DD / 4 + 255) / 256, 256>>>(Wqkv, wqh, wql, D3 * DD / 4);
    split_kernel<<<(DD * DD / 4 + 255) / 256, 256>>>(Wout, woh, wol, DD * DD / 4);

    // 1) QKV projection -> bf16 hi/lo qkv, Q pre-scaled by 0.125
    gemm_bf16x3_kernel<1><<<dim3(D3 / 128, MM / 128), 256, GSMEM>>>(
        xh, xl, wqh, wql, nullptr, qkvh, qkvl, D3);

    // 2) Causal flash attention (HMMA, split bf16) -> bf16 hi/lo att
    flash_hmma_kernel<<<dim3(LL / 128, BB * HH), 256>>>(qkvh, qkvl, ah, al);

    // 3) Output projection -> fp32 d_out
    gemm_bf16x3_kernel<0><<<dim3(DD / 128, MM / 128), 256, GSMEM>>>(
        ah, al, woh, wol, out, nullptr, nullptr, DD);
}

// round 11
// speedup vs baseline: 2.3433x; 1.1368x over previous
#include <cuda_runtime.h>
#include <cuda_bf16.h>
#include <cstdint>
#include <cstddef>

// Problem constants
#define BB 4
#define LL 2048
#define DD 1024
#define HH 16
#define HD 64
#define MM (BB * LL)          // 8192
#define D3 (3 * DD)           // 3072

// ---------------------------------------------------------------------------
// Scratch (device globals)
// ---------------------------------------------------------------------------
__device__ __nv_bfloat16 g_qkvh[(size_t)MM * D3], g_qkvl[(size_t)MM * D3];
__device__ __nv_bfloat16 g_xh[(size_t)MM * DD],  g_xl[(size_t)MM * DD];
__device__ __nv_bfloat16 g_wqh[(size_t)D3 * DD], g_wql[(size_t)D3 * DD];
__device__ __nv_bfloat16 g_woh[(size_t)DD * DD], g_wol[(size_t)DD * DD];
__device__ __nv_bfloat16 g_ah[(size_t)MM * DD],  g_al[(size_t)MM * DD];

// ---------------------------------------------------------------------------
// Common helpers
// ---------------------------------------------------------------------------
__device__ __forceinline__ uint32_t smem_u32(const void* p) {
    uint32_t a;
    asm("{ .reg .u64 t; cvta.to.shared.u64 t, %1; cvt.u32.u64 %0, t; }"
        : "=r"(a) : "l"(p));
    return a;
}
__device__ __forceinline__ void cp16(uint32_t saddr, const void* gaddr) {
    asm volatile("cp.async.cg.shared.global [%0], [%1], 16;"
                 :: "r"(saddr), "l"(gaddr));
}
__device__ __forceinline__ void cp_commit() {
    asm volatile("cp.async.commit_group;" ::: "memory");
}
template<int N> __device__ __forceinline__ void cp_wait() {
    asm volatile("cp.async.wait_group %0;" :: "n"(N) : "memory");
}
__device__ __forceinline__ void ldsm4(uint32_t& r0, uint32_t& r1, uint32_t& r2,
                                      uint32_t& r3, uint32_t addr) {
    asm volatile("ldmatrix.sync.aligned.m8n8.x4.shared.b16 {%0,%1,%2,%3}, [%4];"
                 : "=r"(r0), "=r"(r1), "=r"(r2), "=r"(r3) : "r"(addr));
}
__device__ __forceinline__ void ldsm4t(uint32_t& r0, uint32_t& r1, uint32_t& r2,
                                       uint32_t& r3, uint32_t addr) {
    asm volatile("ldmatrix.sync.aligned.m8n8.x4.trans.shared.b16 {%0,%1,%2,%3}, [%4];"
                 : "=r"(r0), "=r"(r1), "=r"(r2), "=r"(r3) : "r"(addr));
}
__device__ __forceinline__ void mma16816(float* d, const uint32_t* a,
                                         uint32_t b0, uint32_t b1) {
    asm volatile(
        "mma.sync.aligned.m16n8k16.row.col.f32.bf16.bf16.f32 "
        "{%0,%1,%2,%3}, {%4,%5,%6,%7}, {%8,%9}, {%0,%1,%2,%3};"
        : "+f"(d[0]), "+f"(d[1]), "+f"(d[2]), "+f"(d[3])
        : "r"(a[0]), "r"(a[1]), "r"(a[2]), "r"(a[3]), "r"(b0), "r"(b1));
}
// pack (x,y) to bf16x2 hi, produce bf16x2 lo residual
__device__ __forceinline__ uint32_t packhl(float x, float y, uint32_t& lo) {
    __nv_bfloat162 hv = __floats2bfloat162_rn(x, y);
    float hx = __bfloat162float(__low2bfloat16(hv));
    float hy = __bfloat162float(__high2bfloat16(hv));
    __nv_bfloat162 lv = __floats2bfloat162_rn(x - hx, y - hy);
    lo = *(uint32_t*)&lv;
    return *(uint32_t*)&hv;
}

// ---------------------------------------------------------------------------
// fp32 -> (bf16 hi, bf16 lo) split (for x and weights)
// ---------------------------------------------------------------------------
__global__ __launch_bounds__(256) void split_kernel(
    const float* __restrict__ src, __nv_bfloat16* __restrict__ hi,
    __nv_bfloat16* __restrict__ lo, int n4)
{
    const int i = blockIdx.x * blockDim.x + threadIdx.x;
    if (i >= n4) return;
    float4 v = *(const float4*)(src + (size_t)i * 4);
    uint32_t l0, l1;
    uint32_t h0 = packhl(v.x, v.y, l0);
    uint32_t h1 = packhl(v.z, v.w, l1);
    *(uint2*)(hi + (size_t)i * 4) = make_uint2(h0, h1);
    *(uint2*)(lo + (size_t)i * 4) = make_uint2(l0, l1);
}

// ---------------------------------------------------------------------------
// mma.sync bf16x3 GEMM, fused-tile version.
// Per 32-wide k-chunk: load Ah, Al, Bh, Bl tiles once, run 3 MMA passes
// (Ah*Bh, Ah*Bl, Al*Bh). BM=BN=128, 8 warps (2m x 4n), warp 64x32.
// 2-stage cp.async pipeline (stage = 4 tiles = 40960 B).
// MODE 0: fp32 C. MODE 1: bf16 hi/lo C, cols < 1024 scaled by 0.125.
// ---------------------------------------------------------------------------
#define ROWB 80
#define TILEB (128 * ROWB)            // 10240
#define STAGEB (4 * TILEB)            // 40960: Ah Al Bh Bl
#define GSMEM (2 * STAGEB)            // 81920
#define NCHUNK 32

template<int MODE>
__global__ __launch_bounds__(256, 2) void gemm_bf16x3_kernel(
    const __nv_bfloat16* __restrict__ Ahi, const __nv_bfloat16* __restrict__ Alo,
    const __nv_bfloat16* __restrict__ Bhi, const __nv_bfloat16* __restrict__ Blo,
    float* __restrict__ C, __nv_bfloat16* __restrict__ Ch,
    __nv_bfloat16* __restrict__ Cl, int Nn)
{
    extern __shared__ char smem[];
    const int tid  = threadIdx.x;
    const int lane = tid & 31;
    const int wid  = tid >> 5;
    const int wm   = wid & 1;
    const int wn   = wid >> 1;
    const int bm   = blockIdx.y * 128;
    const int bn   = blockIdx.x * 128;

    const uint32_t sb = smem_u32(smem);

    // load mapping: 2 x 16B chunks per tile per thread (512 chunks per tile)
    const int f0 = tid * 2;
    const int r0_ = f0 >> 2, c0_ = f0 & 3;
    const int r1_ = (f0 + 1) >> 2, c1_ = (f0 + 1) & 3;
    const uint32_t s0 = (uint32_t)(r0_ * ROWB + c0_ * 16);
    const uint32_t s1 = (uint32_t)(r1_ * ROWB + c1_ * 16);

    // gmem base pointers for this thread's two chunks (advance 32/chunk)
    const __nv_bfloat16* gA0h = Ahi + (size_t)(bm + r0_) * DD + c0_ * 8;
    const __nv_bfloat16* gA1h = Ahi + (size_t)(bm + r1_) * DD + c1_ * 8;
    const __nv_bfloat16* gA0l = Alo + (size_t)(bm + r0_) * DD + c0_ * 8;
    const __nv_bfloat16* gA1l = Alo + (size_t)(bm + r1_) * DD + c1_ * 8;
    const __nv_bfloat16* gB0h = Bhi + (size_t)(bn + r0_) * DD + c0_ * 8;
    const __nv_bfloat16* gB1h = Bhi + (size_t)(bn + r1_) * DD + c1_ * 8;
    const __nv_bfloat16* gB0l = Blo + (size_t)(bn + r0_) * DD + c0_ * 8;
    const __nv_bfloat16* gB1l = Blo + (size_t)(bn + r1_) * DD + c1_ * 8;

    const uint32_t lm_row = (lane & 15);
    const uint32_t lm_hi  = (lane >> 4) * 16;
    const uint32_t a_base = (wm * 64 + lm_row) * ROWB + lm_hi;
    const uint32_t b_base = (wn * 32 + lm_row) * ROWB + lm_hi;

    float acc[4][4][4];
#pragma unroll
    for (int i = 0; i < 4; i++)
#pragma unroll
        for (int j = 0; j < 4; j++)
#pragma unroll
            for (int k = 0; k < 4; k++) acc[i][j][k] = 0.f;

    auto issue_loads = [&](int kt) {
        const uint32_t st = sb + (uint32_t)(kt & 1) * STAGEB;
        const int ko = kt * 32;
        cp16(st + s0,             gA0h + ko);
        cp16(st + s1,             gA1h + ko);
        cp16(st + TILEB + s0,     gA0l + ko);
        cp16(st + TILEB + s1,     gA1l + ko);
        cp16(st + 2 * TILEB + s0, gB0h + ko);
        cp16(st + 2 * TILEB + s1, gB1h + ko);
        cp16(st + 3 * TILEB + s0, gB0l + ko);
        cp16(st + 3 * TILEB + s1, gB1l + ko);
    };

    issue_loads(0); cp_commit();

    for (int kt = 0; kt < NCHUNK; kt++) {
        cp_wait<0>();
        __syncthreads();
        if (kt + 1 < NCHUNK) { issue_loads(kt + 1); cp_commit(); }

        const uint32_t st = sb + (uint32_t)(kt & 1) * STAGEB;
#pragma unroll
        for (int s = 0; s < 2; s++) {
            const uint32_t sof = s * 32;
            uint32_t ah[4][4], bh[2][4];
#pragma unroll
            for (int mf = 0; mf < 4; mf++)
                ldsm4(ah[mf][0], ah[mf][1], ah[mf][2], ah[mf][3],
                      st + a_base + mf * 16 * ROWB + sof);
#pragma unroll
            for (int i = 0; i < 2; i++)
                ldsm4(bh[i][0], bh[i][1], bh[i][2], bh[i][3],
                      st + 2 * TILEB + b_base + i * 16 * ROWB + sof);
            // pass 1: Ah * Bh
#pragma unroll
            for (int mf = 0; mf < 4; mf++)
#pragma unroll
                for (int nf = 0; nf < 4; nf++) {
                    const int i = nf >> 1, sub = nf & 1;
                    mma16816(acc[mf][nf], ah[mf],
                             sub ? bh[i][1] : bh[i][0], sub ? bh[i][3] : bh[i][2]);
                }
            // pass 2: Ah * Bl
            {
                uint32_t bl[2][4];
#pragma unroll
                for (int i = 0; i < 2; i++)
                    ldsm4(bl[i][0], bl[i][1], bl[i][2], bl[i][3],
                          st + 3 * TILEB + b_base + i * 16 * ROWB + sof);
#pragma unroll
                for (int mf = 0; mf < 4; mf++)
#pragma unroll
                    for (int nf = 0; nf < 4; nf++) {
                        const int i = nf >> 1, sub = nf & 1;
                        mma16816(acc[mf][nf], ah[mf],
                                 sub ? bl[i][1] : bl[i][0], sub ? bl[i][3] : bl[i][2]);
                    }
            }
            // pass 3: Al * Bh
            {
                uint32_t al4[4][4];
#pragma unroll
                for (int mf = 0; mf < 4; mf++)
                    ldsm4(al4[mf][0], al4[mf][1], al4[mf][2], al4[mf][3],
                          st + TILEB + a_base + mf * 16 * ROWB + sof);
#pragma unroll
                for (int mf = 0; mf < 4; mf++)
#pragma unroll
                    for (int nf = 0; nf < 4; nf++) {
                        const int i = nf >> 1, sub = nf & 1;
                        mma16816(acc[mf][nf], al4[mf],
                                 sub ? bh[i][1] : bh[i][0], sub ? bh[i][3] : bh[i][2]);
                    }
            }
        }
    }

    // Epilogue
    const int er = lane >> 2;
    const int ec = (lane & 3) * 2;
    const float qs = (MODE == 1 && bn < DD) ? 0.125f : 1.0f;
#pragma unroll
    for (int mf = 0; mf < 4; mf++) {
        const size_t row0 = (size_t)(bm + wm * 64 + mf * 16 + er) * Nn + bn + wn * 32;
        const size_t row8 = row0 + (size_t)8 * Nn;
#pragma unroll
        for (int nf = 0; nf < 4; nf++) {
            if (MODE == 0) {
                *(float2*)(C + row0 + nf * 8 + ec) = make_float2(acc[mf][nf][0], acc[mf][nf][1]);
                *(float2*)(C + row8 + nf * 8 + ec) = make_float2(acc[mf][nf][2], acc[mf][nf][3]);
            } else {
                uint32_t lo;
                uint32_t hi = packhl(acc[mf][nf][0] * qs, acc[mf][nf][1] * qs, lo);
                *(uint32_t*)(Ch + row0 + nf * 8 + ec) = hi;
                *(uint32_t*)(Cl + row0 + nf * 8 + ec) = lo;
                hi = packhl(acc[mf][nf][2] * qs, acc[mf][nf][3] * qs, lo);
                *(uint32_t*)(Ch + row8 + nf * 8 + ec) = hi;
                *(uint32_t*)(Cl + row8 + nf * 8 + ec) = lo;
            }
        }
    }
}

// ---------------------------------------------------------------------------
// Flash attention on HMMA, split bf16 precision, fp32 softmax.
// ---------------------------------------------------------------------------
#define FROWB 144

__global__ __launch_bounds__(256) void flash_hmma_kernel(
    const __nv_bfloat16* __restrict__ qh_, const __nv_bfloat16* __restrict__ ql_,
    __nv_bfloat16* __restrict__ oh_, __nv_bfloat16* __restrict__ ol_)
{
    __shared__ __align__(16) char fs[4 * 64 * FROWB];   // 36864
    const int bh = blockIdx.y;
    const int b  = bh >> 4;
    const int h  = bh & 15;
    const int qbase = blockIdx.x * 128;
    const int tid = threadIdx.x, lane = tid & 31, w = tid >> 5;
    const uint32_t sb = smem_u32(fs);

    const size_t qrow0 = (size_t)b * LL + qbase;
#pragma unroll
    for (int it = 0; it < 8; it++) {
        const int f = it * 256 + tid;
        const __nv_bfloat16* src = (f & 1024) ? ql_ : qh_;
        const int idx = f & 1023, r = idx >> 3, c = idx & 7;
        uint4 v = *(const uint4*)(src + (qrow0 + r) * D3 + h * HD + c * 8);
        *(uint4*)(fs + ((f >> 10) ? 18432 : 0) + r * FROWB + c * 16) = v;
    }
    __syncthreads();

    uint32_t qfh[4][4], qfl[4][4];
    {
        const uint32_t qa = sb + (uint32_t)((w * 16 + (lane & 15)) * FROWB
                                            + ((lane >> 4) * 16));
#pragma unroll
        for (int kc = 0; kc < 4; kc++) {
            ldsm4(qfh[kc][0], qfh[kc][1], qfh[kc][2], qfh[kc][3], qa + kc * 32);
            ldsm4(qfl[kc][0], qfl[kc][1], qfl[kc][2], qfl[kc][3],
                  qa + 18432 + kc * 32);
        }
    }

    float o[8][4];
#pragma unroll
    for (int i = 0; i < 8; i++)
#pragma unroll
        for (int j = 0; j < 4; j++) o[i][j] = 0.f;
    float m0 = -1e30f, m1 = -1e30f, l0 = 0.f, l1 = 0.f;
    const int row0 = qbase + w * 16 + (lane >> 2);
    const int ntiles = (qbase >> 6) + 2;

    for (int t = 0; t < ntiles; t++) {
        const int kvbase = t * 64;
        __syncthreads();
#pragma unroll
        for (int it = 0; it < 8; it++) {
            const int f = it * 256 + tid;
            const int arr = f >> 9, idx = f & 511, r = idx >> 3, c = idx & 7;
            const __nv_bfloat16* src = (arr & 1) ? ql_ : qh_;
            const int colb = (arr < 2) ? (DD + h * HD) : (2 * DD + h * HD);
            uint4 v = *(const uint4*)(src + ((size_t)b * LL + kvbase + r) * D3
                                      + colb + c * 8);
            *(uint4*)(fs + arr * 9216 + r * FROWB + c * 16) = v;
        }
        __syncthreads();

        if (kvbase > qbase + w * 16 + 15) continue;

        float s[8][4];
#pragma unroll
        for (int i = 0; i < 8; i++)
#pragma unroll
            for (int j = 0; j < 4; j++) s[i][j] = 0.f;
#pragma unroll
        for (int nt2 = 0; nt2 < 4; nt2++) {
#pragma unroll
            for (int kc = 0; kc < 4; kc++) {
                uint32_t kh4[4], kl4[4];
                const uint32_t ka = sb + (uint32_t)((nt2 * 16 + (lane & 15)) * FROWB
                                    + ((lane >> 4) * 16) + kc * 32);
                ldsm4(kh4[0], kh4[1], kh4[2], kh4[3], ka);
                ldsm4(kl4[0], kl4[1], kl4[2], kl4[3], ka + 9216);
                mma16816(s[2 * nt2],     qfh[kc], kh4[0], kh4[2]);
                mma16816(s[2 * nt2],     qfh[kc], kl4[0], kl4[2]);
                mma16816(s[2 * nt2],     qfl[kc], kh4[0], kh4[2]);
                mma16816(s[2 * nt2 + 1], qfh[kc], kh4[1], kh4[3]);
                mma16816(s[2 * nt2 + 1], qfh[kc], kl4[1], kl4[3]);
                mma16816(s[2 * nt2 + 1], qfl[kc], kh4[1], kh4[3]);
            }
        }

        if (kvbase + 63 > qbase + w * 16) {
#pragma unroll
            for (int t8 = 0; t8 < 8; t8++) {
                const int c0 = kvbase + t8 * 8 + (lane & 3) * 2;
                if (c0 > row0)         s[t8][0] = -1e30f;
                if (c0 + 1 > row0)     s[t8][1] = -1e30f;
                if (c0 > row0 + 8)     s[t8][2] = -1e30f;
                if (c0 + 1 > row0 + 8) s[t8][3] = -1e30f;
            }
        }

        float tm0 = -1e30f, tm1 = -1e30f;
#pragma unroll
        for (int t8 = 0; t8 < 8; t8++) {
            tm0 = fmaxf(tm0, fmaxf(s[t8][0], s[t8][1]));
            tm1 = fmaxf(tm1, fmaxf(s[t8][2], s[t8][3]));
        }
        tm0 = fmaxf(tm0, __shfl_xor_sync(0xFFFFFFFFu, tm0, 1));
        tm0 = fmaxf(tm0, __shfl_xor_sync(0xFFFFFFFFu, tm0, 2));
        tm1 = fmaxf(tm1, __shfl_xor_sync(0xFFFFFFFFu, tm1, 1));
        tm1 = fmaxf(tm1, __shfl_xor_sync(0xFFFFFFFFu, tm1, 2));
        const float mn0 = fmaxf(m0, tm0), mn1 = fmaxf(m1, tm1);
        const float a0 = __expf(m0 - mn0), a1 = __expf(m1 - mn1);
        m0 = mn0; m1 = mn1;
        float rs0 = 0.f, rs1 = 0.f;
#pragma unroll
        for (int t8 = 0; t8 < 8; t8++) {
            s[t8][0] = __expf(s[t8][0] - m0);
            s[t8][1] = __expf(s[t8][1] - m0);
            s[t8][2] = __expf(s[t8][2] - m1);
            s[t8][3] = __expf(s[t8][3] - m1);
            rs0 += s[t8][0] + s[t8][1];
            rs1 += s[t8][2] + s[t8][3];
        }
        l0 = l0 * a0 + rs0;
        l1 = l1 * a1 + rs1;
#pragma unroll
        for (int dt = 0; dt < 8; dt++) {
            o[dt][0] *= a0; o[dt][1] *= a0;
            o[dt][2] *= a1; o[dt][3] *= a1;
        }

        uint32_t ph[4][4], pl[4][4];
#pragma unroll
        for (int kc = 0; kc < 4; kc++) {
            ph[kc][0] = packhl(s[2 * kc][0],     s[2 * kc][1],     pl[kc][0]);
            ph[kc][1] = packhl(s[2 * kc][2],     s[2 * kc][3],     pl[kc][1]);
            ph[kc][2] = packhl(s[2 * kc + 1][0], s[2 * kc + 1][1], pl[kc][2]);
            ph[kc][3] = packhl(s[2 * kc + 1][2], s[2 * kc + 1][3], pl[kc][3]);
        }

#pragma unroll
        for (int dt2 = 0; dt2 < 4; dt2++) {
#pragma unroll
            for (int kc = 0; kc < 4; kc++) {
                uint32_t vh4[4], vl4[4];
                const uint32_t va = sb + 18432
                    + (uint32_t)((kc * 16 + ((lane >> 3) & 1) * 8 + (lane & 7)) * FROWB
                                 + (dt2 * 16 + (lane >> 4) * 8) * 2);
                ldsm4t(vh4[0], vh4[1], vh4[2], vh4[3], va);
                ldsm4t(vl4[0], vl4[1], vl4[2], vl4[3], va + 9216);
                mma16816(o[2 * dt2],     ph[kc], vh4[0], vh4[1]);
                mma16816(o[2 * dt2 + 1], ph[kc], vh4[2], vh4[3]);
                mma16816(o[2 * dt2],     ph[kc], vl4[0], vl4[1]);
                mma16816(o[2 * dt2 + 1], ph[kc], vl4[2], vl4[3]);
                mma16816(o[2 * dt2],     pl[kc], vh4[0], vh4[1]);
                mma16816(o[2 * dt2 + 1], pl[kc], vh4[2], vh4[3]);
            }
        }
    }

    l0 += __shfl_xor_sync(0xFFFFFFFFu, l0, 1);
    l0 += __shfl_xor_sync(0xFFFFFFFFu, l0, 2);
    l1 += __shfl_xor_sync(0xFFFFFFFFu, l1, 1);
    l1 += __shfl_xor_sync(0xFFFFFFFFu, l1, 2);
    const float inv0 = 1.f / l0, inv1 = 1.f / l1;
    const size_t gr0 = (size_t)b * LL + qbase + w * 16 + (lane >> 2);
    const int gc0 = h * HD + (lane & 3) * 2;
#pragma unroll
    for (int t8 = 0; t8 < 8; t8++) {
        uint32_t lo;
        uint32_t hi = packhl(o[t8][0] * inv0, o[t8][1] * inv0, lo);
        *(uint32_t*)(oh_ + gr0 * DD + gc0 + t8 * 8) = hi;
        *(uint32_t*)(ol_ + gr0 * DD + gc0 + t8 * 8) = lo;
        hi = packhl(o[t8][2] * inv1, o[t8][3] * inv1, lo);
        *(uint32_t*)(oh_ + (gr0 + 8) * DD + gc0 + t8 * 8) = hi;
        *(uint32_t*)(ol_ + (gr0 + 8) * DD + gc0 + t8 * 8) = lo;
    }
}

// ---------------------------------------------------------------------------
// Launch
// ---------------------------------------------------------------------------
extern "C" void kernel_launch(void* const* d_in, const int* in_sizes, int n_in,
                              void* d_out, int out_size)
{
    const float* x    = (const float*)d_in[0];
    const float* Wqkv = (const float*)d_in[1];
    const float* Wout = (const float*)d_in[2];
    if (n_in >= 3 && in_sizes[1] == DD * DD && in_sizes[2] == 3 * DD * DD) {
        const float* t = Wqkv; Wqkv = Wout; Wout = t;
    }
    float* out = (float*)d_out;

    __nv_bfloat16 *qkvh, *qkvl, *xh, *xl, *wqh, *wql, *woh, *wol, *ah, *al;
    cudaGetSymbolAddress((void**)&qkvh, g_qkvh); cudaGetSymbolAddress((void**)&qkvl, g_qkvl);
    cudaGetSymbolAddress((void**)&xh, g_xh);     cudaGetSymbolAddress((void**)&xl, g_xl);
    cudaGetSymbolAddress((void**)&wqh, g_wqh);   cudaGetSymbolAddress((void**)&wql, g_wql);
    cudaGetSymbolAddress((void**)&woh, g_woh);   cudaGetSymbolAddress((void**)&wol, g_wol);
    cudaGetSymbolAddress((void**)&ah, g_ah);     cudaGetSymbolAddress((void**)&al, g_al);

    cudaFuncSetAttribute(gemm_bf16x3_kernel<0>,
                         cudaFuncAttributeMaxDynamicSharedMemorySize, GSMEM);
    cudaFuncSetAttribute(gemm_bf16x3_kernel<1>,
                         cudaFuncAttributeMaxDynamicSharedMemorySize, GSMEM);

    // Split inputs to (hi, lo) bf16
    split_kernel<<<(MM * DD / 4 + 255) / 256, 256>>>(x, xh, xl, MM * DD / 4);
    split_kernel<<<(D3 * DD / 4 + 255) / 256, 256>>>(Wqkv, wqh, wql, D3 * DD / 4);
    split_kernel<<<(DD * DD / 4 + 255) / 256, 256>>>(Wout, woh, wol, DD * DD / 4);

    // 1) QKV projection -> bf16 hi/lo qkv, Q pre-scaled by 0.125
    gemm_bf16x3_kernel<1><<<dim3(D3 / 128, MM / 128), 256, GSMEM>>>(
        xh, xl, wqh, wql, nullptr, qkvh, qkvl, D3);

    // 2) Causal flash attention (HMMA, split bf16) -> bf16 hi/lo att
    flash_hmma_kernel<<<dim3(LL / 128, BB * HH), 256>>>(qkvh, qkvl, ah, al);

    // 3) Output projection -> fp32 d_out
    gemm_bf16x3_kernel<0><<<dim3(DD / 128, MM / 128), 256, GSMEM>>>(
        ah, al, woh, wol, out, nullptr, nullptr, DD);
}

// round 12
// speedup vs baseline: 3.2532x; 1.3883x over previous
#include <cuda_runtime.h>
#include <cuda_fp16.h>
#include <cstdint>
#include <cstddef>

// Problem constants
#define BB 4
#define LL 2048
#define DD 1024
#define HH 16
#define HD 64
#define MM (BB * LL)          // 8192
#define D3 (3 * DD)           // 3072

// ---------------------------------------------------------------------------
// Scratch (device globals)
// ---------------------------------------------------------------------------
__device__ __half g_qkvh[(size_t)MM * D3];   // fp16 qkv (hi)
__device__ __half g_qkvl[(size_t)MM * D3];   // fp16 qkv residual (Q cols only)
__device__ __half g_xh[(size_t)MM * DD], g_xl[(size_t)MM * DD];
__device__ __half g_wqh[(size_t)D3 * DD];
__device__ __half g_woh[(size_t)DD * DD];
__device__ __half g_oh[(size_t)MM * DD], g_ol[(size_t)MM * DD];

// ---------------------------------------------------------------------------
// Helpers
// ---------------------------------------------------------------------------
__device__ __forceinline__ uint32_t smem_u32(const void* p) {
    uint32_t a;
    asm("{ .reg .u64 t; cvta.to.shared.u64 t, %1; cvt.u32.u64 %0, t; }"
        : "=r"(a) : "l"(p));
    return a;
}
__device__ __forceinline__ void cp16(uint32_t saddr, const void* gaddr) {
    asm volatile("cp.async.cg.shared.global [%0], [%1], 16;"
                 :: "r"(saddr), "l"(gaddr));
}
__device__ __forceinline__ void cp_commit() {
    asm volatile("cp.async.commit_group;" ::: "memory");
}
template<int N> __device__ __forceinline__ void cp_wait() {
    asm volatile("cp.async.wait_group %0;" :: "n"(N) : "memory");
}
__device__ __forceinline__ void ldsm4(uint32_t& r0, uint32_t& r1, uint32_t& r2,
                                      uint32_t& r3, uint32_t addr) {
    asm volatile("ldmatrix.sync.aligned.m8n8.x4.shared.b16 {%0,%1,%2,%3}, [%4];"
                 : "=r"(r0), "=r"(r1), "=r"(r2), "=r"(r3) : "r"(addr));
}
__device__ __forceinline__ void ldsm4t(uint32_t& r0, uint32_t& r1, uint32_t& r2,
                                       uint32_t& r3, uint32_t addr) {
    asm volatile("ldmatrix.sync.aligned.m8n8.x4.trans.shared.b16 {%0,%1,%2,%3}, [%4];"
                 : "=r"(r0), "=r"(r1), "=r"(r2), "=r"(r3) : "r"(addr));
}
// fp16 HMMA m16n8k16, fp32 accumulate
__device__ __forceinline__ void mma16816h(float* d, const uint32_t* a,
                                          uint32_t b0, uint32_t b1) {
    asm volatile(
        "mma.sync.aligned.m16n8k16.row.col.f32.f16.f16.f32 "
        "{%0,%1,%2,%3}, {%4,%5,%6,%7}, {%8,%9}, {%0,%1,%2,%3};"
        : "+f"(d[0]), "+f"(d[1]), "+f"(d[2]), "+f"(d[3])
        : "r"(a[0]), "r"(a[1]), "r"(a[2]), "r"(a[3]), "r"(b0), "r"(b1));
}
// pack (x,y) to fp16x2 hi, produce fp16x2 lo residual
__device__ __forceinline__ uint32_t packhl(float x, float y, uint32_t& lo) {
    __half2 hv = __floats2half2_rn(x, y);
    float hx = __half2float(__low2half(hv));
    float hy = __half2float(__high2half(hv));
    __half2 lv = __floats2half2_rn(x - hx, y - hy);
    lo = *(uint32_t*)&lv;
    return *(uint32_t*)&hv;
}

// ---------------------------------------------------------------------------
// fp32 -> fp16 hi/lo split (x), fp32 -> fp16 convert (weights)
// ---------------------------------------------------------------------------
__global__ __launch_bounds__(256) void split16_kernel(
    const float* __restrict__ src, __half* __restrict__ hi,
    __half* __restrict__ lo, int n4)
{
    const int i = blockIdx.x * blockDim.x + threadIdx.x;
    if (i >= n4) return;
    float4 v = *(const float4*)(src + (size_t)i * 4);
    uint32_t l0, l1;
    uint32_t h0 = packhl(v.x, v.y, l0);
    uint32_t h1 = packhl(v.z, v.w, l1);
    *(uint2*)(hi + (size_t)i * 4) = make_uint2(h0, h1);
    *(uint2*)(lo + (size_t)i * 4) = make_uint2(l0, l1);
}
__global__ __launch_bounds__(256) void cvt16_kernel(
    const float* __restrict__ src, __half* __restrict__ hi, int n4)
{
    const int i = blockIdx.x * blockDim.x + threadIdx.x;
    if (i >= n4) return;
    float4 v = *(const float4*)(src + (size_t)i * 4);
    __half2 h0 = __floats2half2_rn(v.x, v.y);
    __half2 h1 = __floats2half2_rn(v.z, v.w);
    *(uint2*)(hi + (size_t)i * 4) = make_uint2(*(uint32_t*)&h0, *(uint32_t*)&h1);
}

// ---------------------------------------------------------------------------
// fp16 A2B1 GEMM:  C = (Ah + Al) @ Bh^T = Ah@Bh^T + Al@Bh^T   (fp32 acc)
// BM=BN=128, BK=32, 8 warps (2m x 4n), warp 64x32. 3-stage cp.async.
// MODE 0: fp32 C.  MODE 1: fp16 hi out everywhere, lo out for cols < 1024,
//                          cols < 1024 scaled by 0.125 (softmax scale on Q).
// ---------------------------------------------------------------------------
#define ROWB 80
#define TILEB (128 * ROWB)            // 10240
#define STAGEB (3 * TILEB)            // 30720: Ah Al Bh
#define GSMEM (3 * STAGEB)            // 92160
#define NCHUNK 32

template<int MODE>
__global__ __launch_bounds__(256, 2) void gemm_f16x2_kernel(
    const __half* __restrict__ Ahi, const __half* __restrict__ Alo,
    const __half* __restrict__ Bhi,
    float* __restrict__ C, __half* __restrict__ Ch, __half* __restrict__ Cl,
    int Nn)
{
    extern __shared__ char smem[];
    const int tid  = threadIdx.x;
    const int lane = tid & 31;
    const int wid  = tid >> 5;
    const int wm   = wid & 1;
    const int wn   = wid >> 1;
    const int bm   = blockIdx.y * 128;
    const int bn   = blockIdx.x * 128;

    const uint32_t sb = smem_u32(smem);

    const int f0 = tid * 2;
    const int r0_ = f0 >> 2, c0_ = f0 & 3;
    const int r1_ = (f0 + 1) >> 2, c1_ = (f0 + 1) & 3;
    const uint32_t s0 = (uint32_t)(r0_ * ROWB + c0_ * 16);
    const uint32_t s1 = (uint32_t)(r1_ * ROWB + c1_ * 16);

    const __half* gA0h = Ahi + (size_t)(bm + r0_) * DD + c0_ * 8;
    const __half* gA1h = Ahi + (size_t)(bm + r1_) * DD + c1_ * 8;
    const __half* gA0l = Alo + (size_t)(bm + r0_) * DD + c0_ * 8;
    const __half* gA1l = Alo + (size_t)(bm + r1_) * DD + c1_ * 8;
    const __half* gB0h = Bhi + (size_t)(bn + r0_) * DD + c0_ * 8;
    const __half* gB1h = Bhi + (size_t)(bn + r1_) * DD + c1_ * 8;

    const uint32_t lm_row = (lane & 15);
    const uint32_t lm_hi  = (lane >> 4) * 16;
    const uint32_t a_base = (wm * 64 + lm_row) * ROWB + lm_hi;
    const uint32_t b_base = (wn * 32 + lm_row) * ROWB + lm_hi;

    float acc[4][4][4];
#pragma unroll
    for (int i = 0; i < 4; i++)
#pragma unroll
        for (int j = 0; j < 4; j++)
#pragma unroll
            for (int k = 0; k < 4; k++) acc[i][j][k] = 0.f;

    auto issue_loads = [&](int kt) {
        const uint32_t st = sb + (uint32_t)(kt % 3) * STAGEB;
        const int ko = kt * 32;
        cp16(st + s0,             gA0h + ko);
        cp16(st + s1,             gA1h + ko);
        cp16(st + TILEB + s0,     gA0l + ko);
        cp16(st + TILEB + s1,     gA1l + ko);
        cp16(st + 2 * TILEB + s0, gB0h + ko);
        cp16(st + 2 * TILEB + s1, gB1h + ko);
    };

    issue_loads(0); cp_commit();
    issue_loads(1); cp_commit();

    for (int kt = 0; kt < NCHUNK; kt++) {
        cp_wait<1>();
        __syncthreads();
        if (kt + 2 < NCHUNK) issue_loads(kt + 2);
        cp_commit();

        const uint32_t st = sb + (uint32_t)(kt % 3) * STAGEB;
#pragma unroll
        for (int s = 0; s < 2; s++) {
            const uint32_t sof = s * 32;
            uint32_t ah[4][4], bh2[2][4];
#pragma unroll
            for (int mf = 0; mf < 4; mf++)
                ldsm4(ah[mf][0], ah[mf][1], ah[mf][2], ah[mf][3],
                      st + a_base + mf * 16 * ROWB + sof);
#pragma unroll
            for (int i = 0; i < 2; i++)
                ldsm4(bh2[i][0], bh2[i][1], bh2[i][2], bh2[i][3],
                      st + 2 * TILEB + b_base + i * 16 * ROWB + sof);
            // pass 1: Ah * Bh
#pragma unroll
            for (int mf = 0; mf < 4; mf++)
#pragma unroll
                for (int nf = 0; nf < 4; nf++) {
                    const int i = nf >> 1, sub = nf & 1;
                    mma16816h(acc[mf][nf], ah[mf],
                              sub ? bh2[i][1] : bh2[i][0],
                              sub ? bh2[i][3] : bh2[i][2]);
                }
            // pass 2: Al * Bh
            {
                uint32_t al4[4][4];
#pragma unroll
                for (int mf = 0; mf < 4; mf++)
                    ldsm4(al4[mf][0], al4[mf][1], al4[mf][2], al4[mf][3],
                          st + TILEB + a_base + mf * 16 * ROWB + sof);
#pragma unroll
                for (int mf = 0; mf < 4; mf++)
#pragma unroll
                    for (int nf = 0; nf < 4; nf++) {
                        const int i = nf >> 1, sub = nf & 1;
                        mma16816h(acc[mf][nf], al4[mf],
                                  sub ? bh2[i][1] : bh2[i][0],
                                  sub ? bh2[i][3] : bh2[i][2]);
                    }
            }
        }
    }

    // Epilogue
    const int er = lane >> 2;
    const int ec = (lane & 3) * 2;
    const float qs = (MODE == 1 && bn < DD) ? 0.125f : 1.0f;
    const bool wlo = (MODE == 1) && (bn < DD);
#pragma unroll
    for (int mf = 0; mf < 4; mf++) {
        const size_t row0 = (size_t)(bm + wm * 64 + mf * 16 + er) * Nn + bn + wn * 32;
        const size_t row8 = row0 + (size_t)8 * Nn;
#pragma unroll
        for (int nf = 0; nf < 4; nf++) {
            if (MODE == 0) {
                *(float2*)(C + row0 + nf * 8 + ec) = make_float2(acc[mf][nf][0], acc[mf][nf][1]);
                *(float2*)(C + row8 + nf * 8 + ec) = make_float2(acc[mf][nf][2], acc[mf][nf][3]);
            } else {
                uint32_t lo;
                uint32_t hi = packhl(acc[mf][nf][0] * qs, acc[mf][nf][1] * qs, lo);
                *(uint32_t*)(Ch + row0 + nf * 8 + ec) = hi;
                if (wlo) *(uint32_t*)(Cl + row0 + nf * 8 + ec) = lo;
                hi = packhl(acc[mf][nf][2] * qs, acc[mf][nf][3] * qs, lo);
                *(uint32_t*)(Ch + row8 + nf * 8 + ec) = hi;
                if (wlo) *(uint32_t*)(Cl + row8 + nf * 8 + ec) = lo;
            }
        }
    }
}

// ---------------------------------------------------------------------------
// Flash attention, fp16 A2B1: S = (Qh+Ql)Kh^T, O = (Ph+Pl)Vh. fp32 softmax.
// CTA: 128 q-rows, 8 warps x 16 rows. KV tile 64, cp.async double-buffered.
// Writes O as fp16 hi/lo (A operand of the out-projection).
// ---------------------------------------------------------------------------
#define FROWB 144

__global__ __launch_bounds__(256) void flash_f16_kernel(
    const __half* __restrict__ qh_, const __half* __restrict__ ql_,
    __half* __restrict__ oh_, __half* __restrict__ ol_)
{
    __shared__ __align__(16) char fs[2 * 128 * FROWB];   // 36864
    const int bh = blockIdx.y;
    const int b  = bh >> 4;
    const int h  = bh & 15;
    const int qbase = blockIdx.x * 128;
    const int tid = threadIdx.x, lane = tid & 31, w = tid >> 5;
    const uint32_t sb = smem_u32(fs);

    // ---- Load Q hi/lo tile (128 x 64 fp16 each) into smem ----
    const size_t qrow0 = (size_t)b * LL + qbase;
#pragma unroll
    for (int it = 0; it < 8; it++) {
        const int f = it * 256 + tid;                   // 0..2047
        const __half* src = (f & 1024) ? ql_ : qh_;
        const int idx = f & 1023, r = idx >> 3, c = idx & 7;
        uint4 v = *(const uint4*)(src + (qrow0 + r) * D3 + h * HD + c * 8);
        *(uint4*)(fs + ((f >> 10) ? 18432 : 0) + r * FROWB + c * 16) = v;
    }
    __syncthreads();

    // ---- Extract Q A-fragments ----
    uint32_t qfh[4][4], qfl[4][4];
    {
        const uint32_t qa = sb + (uint32_t)((w * 16 + (lane & 15)) * FROWB
                                            + ((lane >> 4) * 16));
#pragma unroll
        for (int kc = 0; kc < 4; kc++) {
            ldsm4(qfh[kc][0], qfh[kc][1], qfh[kc][2], qfh[kc][3], qa + kc * 32);
            ldsm4(qfl[kc][0], qfl[kc][1], qfl[kc][2], qfl[kc][3],
                  qa + 18432 + kc * 32);
        }
    }
    __syncthreads();   // Q smem now reusable as KV buffers

    float o[8][4];
#pragma unroll
    for (int i = 0; i < 8; i++)
#pragma unroll
        for (int j = 0; j < 4; j++) o[i][j] = 0.f;
    float m0 = -1e30f, m1 = -1e30f, l0 = 0.f, l1 = 0.f;
    const int row0 = qbase + w * 16 + (lane >> 2);
    const int ntiles = (qbase >> 6) + 2;

    // KV tile load via cp.async: Kh at buf+0, Vh at buf+9216; buf = (t&1)*18432
    auto issue_kv = [&](int t) {
        const uint32_t dstb = sb + (uint32_t)(t & 1) * 18432;
#pragma unroll
        for (int it = 0; it < 4; it++) {
            const int f = it * 256 + tid;               // 0..1023
            const int arr = f >> 9, idx = f & 511, r = idx >> 3, c = idx & 7;
            cp16(dstb + arr * 9216 + (uint32_t)(r * FROWB + c * 16),
                 qh_ + ((size_t)b * LL + t * 64 + r) * D3
                     + (arr ? 2 * DD : DD) + h * HD + c * 8);
        }
    };

    issue_kv(0); cp_commit();

    for (int t = 0; t < ntiles; t++) {
        cp_wait<0>();
        __syncthreads();
        if (t + 1 < ntiles) issue_kv(t + 1);
        cp_commit();

        const int kvbase = t * 64;
        if (kvbase > qbase + w * 16 + 15) continue;     // fully masked for warp
        const uint32_t buf = sb + (uint32_t)(t & 1) * 18432;

        // ---- S = (Qh + Ql) Kh^T ----
        float s[8][4];
#pragma unroll
        for (int i = 0; i < 8; i++)
#pragma unroll
            for (int j = 0; j < 4; j++) s[i][j] = 0.f;
#pragma unroll
        for (int nt2 = 0; nt2 < 4; nt2++) {
#pragma unroll
            for (int kc = 0; kc < 4; kc++) {
                uint32_t kh4[4];
                const uint32_t ka = buf + (uint32_t)((nt2 * 16 + (lane & 15)) * FROWB
                                    + ((lane >> 4) * 16) + kc * 32);
                ldsm4(kh4[0], kh4[1], kh4[2], kh4[3], ka);
                mma16816h(s[2 * nt2],     qfh[kc], kh4[0], kh4[2]);
                mma16816h(s[2 * nt2],     qfl[kc], kh4[0], kh4[2]);
                mma16816h(s[2 * nt2 + 1], qfh[kc], kh4[1], kh4[3]);
                mma16816h(s[2 * nt2 + 1], qfl[kc], kh4[1], kh4[3]);
            }
        }

        // ---- Causal mask ----
        if (kvbase + 63 > qbase + w * 16) {
#pragma unroll
            for (int t8 = 0; t8 < 8; t8++) {
                const int c0 = kvbase + t8 * 8 + (lane & 3) * 2;
                if (c0 > row0)         s[t8][0] = -1e30f;
                if (c0 + 1 > row0)     s[t8][1] = -1e30f;
                if (c0 > row0 + 8)     s[t8][2] = -1e30f;
                if (c0 + 1 > row0 + 8) s[t8][3] = -1e30f;
            }
        }

        // ---- Online softmax (registers + shfl) ----
        float tm0 = -1e30f, tm1 = -1e30f;
#pragma unroll
        for (int t8 = 0; t8 < 8; t8++) {
            tm0 = fmaxf(tm0, fmaxf(s[t8][0], s[t8][1]));
            tm1 = fmaxf(tm1, fmaxf(s[t8][2], s[t8][3]));
        }
        tm0 = fmaxf(tm0, __shfl_xor_sync(0xFFFFFFFFu, tm0, 1));
        tm0 = fmaxf(tm0, __shfl_xor_sync(0xFFFFFFFFu, tm0, 2));
        tm1 = fmaxf(tm1, __shfl_xor_sync(0xFFFFFFFFu, tm1, 1));
        tm1 = fmaxf(tm1, __shfl_xor_sync(0xFFFFFFFFu, tm1, 2));
        const float mn0 = fmaxf(m0, tm0), mn1 = fmaxf(m1, tm1);
        const float a0 = __expf(m0 - mn0), a1 = __expf(m1 - mn1);
        m0 = mn0; m1 = mn1;
        float rs0 = 0.f, rs1 = 0.f;
#pragma unroll
        for (int t8 = 0; t8 < 8; t8++) {
            s[t8][0] = __expf(s[t8][0] - m0);
            s[t8][1] = __expf(s[t8][1] - m0);
            s[t8][2] = __expf(s[t8][2] - m1);
            s[t8][3] = __expf(s[t8][3] - m1);
            rs0 += s[t8][0] + s[t8][1];
            rs1 += s[t8][2] + s[t8][3];
        }
        l0 = l0 * a0 + rs0;
        l1 = l1 * a1 + rs1;
#pragma unroll
        for (int dt = 0; dt < 8; dt++) {
            o[dt][0] *= a0; o[dt][1] *= a0;
            o[dt][2] *= a1; o[dt][3] *= a1;
        }

        // ---- P -> fp16 hi/lo A-fragments ----
        uint32_t ph[4][4], pl[4][4];
#pragma unroll
        for (int kc = 0; kc < 4; kc++) {
            ph[kc][0] = packhl(s[2 * kc][0],     s[2 * kc][1],     pl[kc][0]);
            ph[kc][1] = packhl(s[2 * kc][2],     s[2 * kc][3],     pl[kc][1]);
            ph[kc][2] = packhl(s[2 * kc + 1][0], s[2 * kc + 1][1], pl[kc][2]);
            ph[kc][3] = packhl(s[2 * kc + 1][2], s[2 * kc + 1][3], pl[kc][3]);
        }

        // ---- O += (Ph + Pl) Vh  (V via ldmatrix.trans) ----
#pragma unroll
        for (int dt2 = 0; dt2 < 4; dt2++) {
#pragma unroll
            for (int kc = 0; kc < 4; kc++) {
                uint32_t vh4[4];
                const uint32_t va = buf + 9216
                    + (uint32_t)((kc * 16 + ((lane >> 3) & 1) * 8 + (lane & 7)) * FROWB
                                 + (dt2 * 16 + (lane >> 4) * 8) * 2);
                ldsm4t(vh4[0], vh4[1], vh4[2], vh4[3], va);
                mma16816h(o[2 * dt2],     ph[kc], vh4[0], vh4[1]);
                mma16816h(o[2 * dt2 + 1], ph[kc], vh4[2], vh4[3]);
                mma16816h(o[2 * dt2],     pl[kc], vh4[0], vh4[1]);
                mma16816h(o[2 * dt2 + 1], pl[kc], vh4[2], vh4[3]);
            }
        }
    }

    // ---- Finalize: reduce l, normalize, write fp16 hi/lo ----
    l0 += __shfl_xor_sync(0xFFFFFFFFu, l0, 1);
    l0 += __shfl_xor_sync(0xFFFFFFFFu, l0, 2);
    l1 += __shfl_xor_sync(0xFFFFFFFFu, l1, 1);
    l1 += __shfl_xor_sync(0xFFFFFFFFu, l1, 2);
    const float inv0 = 1.f / l0, inv1 = 1.f / l1;
    const size_t gr0 = (size_t)b * LL + qbase + w * 16 + (lane >> 2);
    const int gc0 = h * HD + (lane & 3) * 2;
#pragma unroll
    for (int t8 = 0; t8 < 8; t8++) {
        uint32_t lo;
        uint32_t hi = packhl(o[t8][0] * inv0, o[t8][1] * inv0, lo);
        *(uint32_t*)(oh_ + gr0 * DD + gc0 + t8 * 8) = hi;
        *(uint32_t*)(ol_ + gr0 * DD + gc0 + t8 * 8) = lo;
        hi = packhl(o[t8][2] * inv1, o[t8][3] * inv1, lo);
        *(uint32_t*)(oh_ + (gr0 + 8) * DD + gc0 + t8 * 8) = hi;
        *(uint32_t*)(ol_ + (gr0 + 8) * DD + gc0 + t8 * 8) = lo;
    }
}

// ---------------------------------------------------------------------------
// Launch
// ---------------------------------------------------------------------------
extern "C" void kernel_launch(void* const* d_in, const int* in_sizes, int n_in,
                              void* d_out, int out_size)
{
    const float* x    = (const float*)d_in[0];
    const float* Wqkv = (const float*)d_in[1];
    const float* Wout = (const float*)d_in[2];
    if (n_in >= 3 && in_sizes[1] == DD * DD && in_sizes[2] == 3 * DD * DD) {
        const float* t = Wqkv; Wqkv = Wout; Wout = t;
    }
    float* out = (float*)d_out;

    __half *qkvh, *qkvl, *xh, *xl, *wqh, *woh, *oh, *ol;
    cudaGetSymbolAddress((void**)&qkvh, g_qkvh);
    cudaGetSymbolAddress((void**)&qkvl, g_qkvl);
    cudaGetSymbolAddress((void**)&xh, g_xh);
    cudaGetSymbolAddress((void**)&xl, g_xl);
    cudaGetSymbolAddress((void**)&wqh, g_wqh);
    cudaGetSymbolAddress((void**)&woh, g_woh);
    cudaGetSymbolAddress((void**)&oh, g_oh);
    cudaGetSymbolAddress((void**)&ol, g_ol);

    cudaFuncSetAttribute(gemm_f16x2_kernel<0>,
                         cudaFuncAttributeMaxDynamicSharedMemorySize, GSMEM);
    cudaFuncSetAttribute(gemm_f16x2_kernel<1>,
                         cudaFuncAttributeMaxDynamicSharedMemorySize, GSMEM);

    // x -> fp16 hi/lo split; weights -> single fp16
    split16_kernel<<<(MM * DD / 4 + 255) / 256, 256>>>(x, xh, xl, MM * DD / 4);
    cvt16_kernel<<<(D3 * DD / 4 + 255) / 256, 256>>>(Wqkv, wqh, D3 * DD / 4);
    cvt16_kernel<<<(DD * DD / 4 + 255) / 256, 256>>>(Wout, woh, DD * DD / 4);

    // 1) QKV projection -> fp16 qkv (hi; lo for Q cols), Q pre-scaled 0.125
    gemm_f16x2_kernel<1><<<dim3(D3 / 128, MM / 128), 256, GSMEM>>>(
        xh, xl, wqh, nullptr, qkvh, qkvl, D3);

    // 2) Causal flash attention -> fp16 hi/lo O
    flash_f16_kernel<<<dim3(LL / 128, BB * HH), 256>>>(qkvh, qkvl, oh, ol);

    // 3) Output projection -> fp32 d_out
    gemm_f16x2_kernel<0><<<dim3(DD / 128, MM / 128), 256, GSMEM>>>(
        oh, ol, woh, out, nullptr, nullptr, DD);
}